// round 2
// baseline (speedup 1.0000x reference)
#include <cuda_runtime.h>
#include <math.h>

// Problem constants
#define GB 64        // B*H batched slices
#define NSEQ 128     // tokens per head
#define SDIM 960     // K/V feature dim

// Scratch (device globals; no allocation allowed)
__device__ float g_Kt[GB * NSEQ * SDIM];       // 31.5 MB
__device__ float g_KVt[GB * NSEQ * SDIM];      // 31.5 MB
__device__ float g_Qt[GB * NSEQ * 512];        // 16.8 MB (reused per branch)
__device__ float g_attn[GB * 512 * SDIM];      // 125.8 MB (reused per branch)
__device__ float g_outpre[8192 * 512];         // 16.8 MB (reused per branch)
__device__ float g_stats[GB * 2];              // mean, rstd per slice

// ---------------------------------------------------------------------------
// Generic tiled GEMM, BM=BN=64, BK=16, 128 threads, 8x4 accumulators.
// TN=false: C[m,n] = alpha * sum_k A[m,k] * B[n,k]   (A: MxK, B: NxK, both row-major)
// TN=true : C[m,n] = alpha * sum_k A[k,m] * B[k,n]   (A: KxM, B: KxN, both row-major)
// All of M, N divisible by 64; K divisible by 16 (guaranteed by problem shapes).
// MODB: per-head weight sharing, B batch index = batch & 7.
// ---------------------------------------------------------------------------
template<bool MODB, bool TN>
__global__ __launch_bounds__(128)
void gemm_kernel(const float* __restrict__ Ab, const float* __restrict__ Bb,
                 float* __restrict__ Cb, int M, int N, int K,
                 long sA, long sB, long sC, float alpha)
{
    __shared__ float As[16][64];
    __shared__ float Bs[16][64];

    const int b = blockIdx.z;
    const float* A = Ab + (long)b * sA;
    const float* B = Bb + (MODB ? (long)(b & 7) : (long)b) * sB;
    float* C = Cb + (long)b * sC;

    const int bm = blockIdx.y * 64;
    const int bn = blockIdx.x * 64;
    const int tid = threadIdx.x;
    const int tx = tid & 15;   // 16 groups along N, 4 cols each
    const int ty = tid >> 4;   // 8 groups along M, 8 rows each

    float acc[8][4];
#pragma unroll
    for (int i = 0; i < 8; i++)
#pragma unroll
        for (int j = 0; j < 4; j++) acc[i][j] = 0.f;

    for (int k0 = 0; k0 < K; k0 += 16) {
        if (TN) {
            // A: K x M (lda = M). Tile rows k0..k0+16, cols bm..bm+64. Direct k-major.
#pragma unroll
            for (int t = 0; t < 2; t++) {
                int slot = tid + t * 128;         // 256 float4 slots
                int kk = slot >> 4, m4 = slot & 15;
                float4 v = *(const float4*)(A + (long)(k0 + kk) * M + bm + m4 * 4);
                *(float4*)(&As[kk][m4 * 4]) = v;
            }
#pragma unroll
            for (int t = 0; t < 2; t++) {
                int slot = tid + t * 128;
                int kk = slot >> 4, n4 = slot & 15;
                float4 v = *(const float4*)(B + (long)(k0 + kk) * N + bn + n4 * 4);
                *(float4*)(&Bs[kk][n4 * 4]) = v;
            }
        } else {
            // A: M x K (lda = K). Load float4 along k, transpose into smem.
#pragma unroll
            for (int t = 0; t < 2; t++) {
                int slot = tid + t * 128;
                int row = slot >> 2, c4 = slot & 3;
                float4 v = *(const float4*)(A + (long)(bm + row) * K + k0 + c4 * 4);
                As[c4 * 4 + 0][row] = v.x; As[c4 * 4 + 1][row] = v.y;
                As[c4 * 4 + 2][row] = v.z; As[c4 * 4 + 3][row] = v.w;
            }
#pragma unroll
            for (int t = 0; t < 2; t++) {
                int slot = tid + t * 128;
                int row = slot >> 2, c4 = slot & 3;
                float4 v = *(const float4*)(B + (long)(bn + row) * K + k0 + c4 * 4);
                Bs[c4 * 4 + 0][row] = v.x; Bs[c4 * 4 + 1][row] = v.y;
                Bs[c4 * 4 + 2][row] = v.z; Bs[c4 * 4 + 3][row] = v.w;
            }
        }
        __syncthreads();

#pragma unroll
        for (int k = 0; k < 16; k++) {
            float a[8], bq[4];
            *(float4*)(a)     = *(const float4*)(&As[k][ty * 8]);
            *(float4*)(a + 4) = *(const float4*)(&As[k][ty * 8 + 4]);
            *(float4*)(bq)    = *(const float4*)(&Bs[k][tx * 4]);
#pragma unroll
            for (int i = 0; i < 8; i++)
#pragma unroll
                for (int j = 0; j < 4; j++)
                    acc[i][j] = fmaf(a[i], bq[j], acc[i][j]);
        }
        __syncthreads();
    }

#pragma unroll
    for (int i = 0; i < 8; i++) {
        float4 v = make_float4(acc[i][0] * alpha, acc[i][1] * alpha,
                               acc[i][2] * alpha, acc[i][3] * alpha);
        *(float4*)(C + (long)(bm + ty * 8 + i) * N + bn + tx * 4) = v;
    }
}

// ---------------------------------------------------------------------------
// InstanceNorm stats: per slice g, mean and rstd over len = C*960 elements.
// ---------------------------------------------------------------------------
__global__ __launch_bounds__(256)
void stats_kernel(const float* __restrict__ attn, int len)
{
    int g = blockIdx.x;
    const float* p = attn + (long)g * len;
    float s = 0.f, s2 = 0.f;
    for (int i = threadIdx.x; i < len; i += 256) {
        float v = p[i];
        s += v;
        s2 = fmaf(v, v, s2);
    }
    __shared__ float sh[16];
#pragma unroll
    for (int o = 16; o > 0; o >>= 1) {
        s  += __shfl_down_sync(0xffffffffu, s,  o);
        s2 += __shfl_down_sync(0xffffffffu, s2, o);
    }
    int w = threadIdx.x >> 5, lane = threadIdx.x & 31;
    if (lane == 0) { sh[w] = s; sh[w + 8] = s2; }
    __syncthreads();
    if (threadIdx.x == 0) {
        float S = 0.f, S2 = 0.f;
        for (int i = 0; i < 8; i++) { S += sh[i]; S2 += sh[i + 8]; }
        float mean = S / (float)len;
        float var = S2 / (float)len - mean * mean;
        g_stats[2 * g]     = mean;
        g_stats[2 * g + 1] = rsqrtf(fmaxf(var, 0.f) + 1e-5f);
    }
}

// ---------------------------------------------------------------------------
// Row softmax over 960, input pre-transformed by (x - mean) * rstd.
// One block (256 threads) per (row c, slice g).
// ---------------------------------------------------------------------------
__global__ __launch_bounds__(256)
void softmax_kernel(float* __restrict__ attn, int C)
{
    long g = blockIdx.y;
    long c = blockIdx.x;
    float* row = attn + (g * C + c) * SDIM;
    float mean = g_stats[2 * g];
    float r    = g_stats[2 * g + 1];
    int tid = threadIdx.x;
    int w = tid >> 5, lane = tid & 31;
    __shared__ float sh[8];

    float v[4];
    float mx = -3.0e38f;
#pragma unroll
    for (int i = 0; i < 4; i++) {
        int idx = tid + i * 256;
        if (idx < SDIM) { v[i] = (row[idx] - mean) * r; mx = fmaxf(mx, v[i]); }
        else            { v[i] = -3.0e38f; }
    }
#pragma unroll
    for (int o = 16; o > 0; o >>= 1) mx = fmaxf(mx, __shfl_xor_sync(0xffffffffu, mx, o));
    if (lane == 0) sh[w] = mx;
    __syncthreads();
    if (w == 0) {
        float m2 = (lane < 8) ? sh[lane] : -3.0e38f;
#pragma unroll
        for (int o = 4; o > 0; o >>= 1) m2 = fmaxf(m2, __shfl_xor_sync(0xffffffffu, m2, o));
        if (lane == 0) sh[0] = m2;
    }
    __syncthreads();
    mx = sh[0];
    __syncthreads();

    float s = 0.f;
#pragma unroll
    for (int i = 0; i < 4; i++) {
        int idx = tid + i * 256;
        if (idx < SDIM) { v[i] = __expf(v[i] - mx); s += v[i]; }
    }
#pragma unroll
    for (int o = 16; o > 0; o >>= 1) s += __shfl_xor_sync(0xffffffffu, s, o);
    if (lane == 0) sh[w] = s;
    __syncthreads();
    if (w == 0) {
        float t = (lane < 8) ? sh[lane] : 0.f;
#pragma unroll
        for (int o = 4; o > 0; o >>= 1) t += __shfl_xor_sync(0xffffffffu, t, o);
        if (lane == 0) sh[0] = t;
    }
    __syncthreads();
    float inv = 1.f / sh[0];
#pragma unroll
    for (int i = 0; i < 4; i++) {
        int idx = tid + i * 256;
        if (idx < SDIM) row[idx] = v[i] * inv;
    }
}

// ---------------------------------------------------------------------------
// Launch sequence (single stream, graph-capturable, allocation-free)
// ---------------------------------------------------------------------------
extern "C" void kernel_launch(void* const* d_in, const int* in_sizes, int n_in,
                              void* d_out, int out_size)
{
    const float* Q[4]  = { (const float*)d_in[0], (const float*)d_in[1],
                           (const float*)d_in[2], (const float*)d_in[3] };
    const float* KV    = (const float*)d_in[4];
    const float* Wk    = (const float*)d_in[5];
    const float* Wv    = (const float*)d_in[6];
    const float* Wq[4] = { (const float*)d_in[7], (const float*)d_in[8],
                           (const float*)d_in[9], (const float*)d_in[10] };
    const float* Wo[4] = { (const float*)d_in[11], (const float*)d_in[12],
                           (const float*)d_in[13], (const float*)d_in[14] };
    float* out = (float*)d_out;

    float *Kt, *KVt, *Qt, *attn, *outpre;
    cudaGetSymbolAddress((void**)&Kt,     g_Kt);
    cudaGetSymbolAddress((void**)&KVt,    g_KVt);
    cudaGetSymbolAddress((void**)&Qt,     g_Qt);
    cudaGetSymbolAddress((void**)&attn,   g_attn);
    cudaGetSymbolAddress((void**)&outpre, g_outpre);

    const float inv_scale = 1.0f / sqrtf((float)SDIM);

    // KV transform: Kt = KV @ Wk^T ; KVt = Kt @ Wv^T   (per-head weights)
    gemm_kernel<true, false><<<dim3(SDIM / 64, NSEQ / 64, GB), 128>>>(
        KV, Wk, Kt, NSEQ, SDIM, SDIM,
        (long)NSEQ * SDIM, (long)SDIM * SDIM, (long)NSEQ * SDIM, 1.f);
    gemm_kernel<true, false><<<dim3(SDIM / 64, NSEQ / 64, GB), 128>>>(
        Kt, Wv, KVt, NSEQ, SDIM, SDIM,
        (long)NSEQ * SDIM, (long)SDIM * SDIM, (long)NSEQ * SDIM, 1.f);

    const int Cs[4] = { 64, 128, 256, 512 };
    long ooff = 0;
    for (int i = 0; i < 4; i++) {
        const int C = Cs[i];

        // Qt = Qh @ Wq^T : [128, C] per slice
        gemm_kernel<true, false><<<dim3(C / 64, NSEQ / 64, GB), 128>>>(
            Q[i], Wq[i], Qt, NSEQ, C, C,
            (long)NSEQ * C, (long)C * C, (long)NSEQ * C, 1.f);

        // attn[c,s] = inv_scale * sum_n Qt[n,c] * KVt[n,s] : [C, 960]
        gemm_kernel<false, true><<<dim3(SDIM / 64, C / 64, GB), 128>>>(
            Qt, KVt, attn, C, SDIM, NSEQ,
            (long)NSEQ * C, (long)NSEQ * SDIM, (long)C * SDIM, inv_scale);

        // InstanceNorm stats + softmax over s
        stats_kernel<<<GB, 256>>>(attn, C * SDIM);
        softmax_kernel<<<dim3(C, GB), 256>>>(attn, C);

        // outpre[n,c] = sum_s KVt[n,s] * attn[c,s] : [128, C] per slice -> [8192, C]
        gemm_kernel<false, false><<<dim3(C / 64, NSEQ / 64, GB), 128>>>(
            KVt, attn, outpre, NSEQ, C, SDIM,
            (long)NSEQ * SDIM, (long)C * SDIM, (long)NSEQ * C, 1.f);

        // Y = outpre @ Wo^T : [8192, C]
        gemm_kernel<false, false><<<dim3(C / 64, 8192 / 64, 1), 128>>>(
            outpre, Wo[i], out + ooff, 8192, C, C, 0, 0, 0, 1.f);

        ooff += 8192L * C;
    }
}

// round 3
// speedup vs baseline: 1.7093x; 1.7093x over previous
#include <cuda_runtime.h>
#include <math.h>

// Problem constants
#define GB 64        // B*H batched slices
#define NSEQ 128     // tokens per head
#define SDIM 960     // K/V feature dim

// Scratch (device globals; no allocation allowed)
__device__ float g_Kt[GB * NSEQ * SDIM];
__device__ float g_KVt[GB * NSEQ * SDIM];
__device__ float g_Qt[GB * NSEQ * 512];
__device__ float g_attn[GB * 512 * SDIM];
__device__ float g_outpre[8192 * 512];
__device__ float g_stats[GB * 2];    // mean, rstd
__device__ float g_red[GB * 2];      // atomic accumulators (self-zeroing)

__device__ __forceinline__ unsigned f2tf32(float x) {
    unsigned u;
    asm("cvt.rna.tf32.f32 %0, %1;" : "=r"(u) : "f"(x));
    return u;
}

// ---------------------------------------------------------------------------
// TF32 tensor-core GEMM, BM=BN=64, BK=16, 128 threads (4 warps, 2x2),
// each warp computes 32x32 via 2x4 m16n8k8 mma tiles.
// TN=false: C[m,n] = alpha * sum_k A[m,k] * B[n,k]   (A: MxK, B: NxK row-major)
// TN=true : C[m,n] = alpha * sum_k A[k,m] * B[k,n]   (A: KxM, B: KxN row-major)
// M,N divisible by 64; K divisible by 16.
// ---------------------------------------------------------------------------
#define SPAD 72   // smem row stride (floats): bank = 8*tg + g -> conflict-free frags

template<bool MODB, bool TN>
__global__ __launch_bounds__(128)
void gemm_tf32(const float* __restrict__ Ab, const float* __restrict__ Bb,
               float* __restrict__ Cb, int M, int N, int K,
               long sA, long sB, long sC, float alpha)
{
    __shared__ float As[16][SPAD];   // [k][m], tf32-rounded
    __shared__ float Bs[16][SPAD];   // [k][n], tf32-rounded

    const int b = blockIdx.z;
    const float* A = Ab + (long)b * sA;
    const float* B = Bb + (MODB ? (long)(b & 7) : (long)b) * sB;
    float* C = Cb + (long)b * sC;

    const int bm = blockIdx.y * 64;
    const int bn = blockIdx.x * 64;
    const int tid  = threadIdx.x;
    const int warp = tid >> 5;
    const int lane = tid & 31;
    const int g  = lane >> 2;     // groupID
    const int tg = lane & 3;      // threadID_in_group
    const int wm = (warp & 1) * 32;
    const int wn = (warp >> 1) * 32;

    float acc[2][4][4];
#pragma unroll
    for (int i = 0; i < 2; i++)
#pragma unroll
        for (int j = 0; j < 4; j++)
#pragma unroll
            for (int c = 0; c < 4; c++) acc[i][j][c] = 0.f;

    const float* Asp = &As[0][0];
    const float* Bsp = &Bs[0][0];

    for (int k0 = 0; k0 < K; k0 += 16) {
        if (TN) {
            // A: KxM. 256 float4 slots: 16 k-rows x 16 m4-groups.
#pragma unroll
            for (int t = 0; t < 2; t++) {
                int slot = tid + t * 128;
                int kk = slot >> 4, m4 = slot & 15;
                float4 v = *(const float4*)(A + (long)(k0 + kk) * M + bm + m4 * 4);
                unsigned r0 = f2tf32(v.x), r1 = f2tf32(v.y), r2 = f2tf32(v.z), r3 = f2tf32(v.w);
                float4 w = make_float4(__uint_as_float(r0), __uint_as_float(r1),
                                       __uint_as_float(r2), __uint_as_float(r3));
                *(float4*)(&As[kk][m4 * 4]) = w;
            }
#pragma unroll
            for (int t = 0; t < 2; t++) {
                int slot = tid + t * 128;
                int kk = slot >> 4, n4 = slot & 15;
                float4 v = *(const float4*)(B + (long)(k0 + kk) * N + bn + n4 * 4);
                unsigned r0 = f2tf32(v.x), r1 = f2tf32(v.y), r2 = f2tf32(v.z), r3 = f2tf32(v.w);
                float4 w = make_float4(__uint_as_float(r0), __uint_as_float(r1),
                                       __uint_as_float(r2), __uint_as_float(r3));
                *(float4*)(&Bs[kk][n4 * 4]) = w;
            }
        } else {
            // A: MxK. float4 along k, transpose into [k][m].
#pragma unroll
            for (int t = 0; t < 2; t++) {
                int slot = tid + t * 128;
                int row = slot >> 2, c4 = slot & 3;
                float4 v = *(const float4*)(A + (long)(bm + row) * K + k0 + c4 * 4);
                As[c4 * 4 + 0][row] = __uint_as_float(f2tf32(v.x));
                As[c4 * 4 + 1][row] = __uint_as_float(f2tf32(v.y));
                As[c4 * 4 + 2][row] = __uint_as_float(f2tf32(v.z));
                As[c4 * 4 + 3][row] = __uint_as_float(f2tf32(v.w));
            }
#pragma unroll
            for (int t = 0; t < 2; t++) {
                int slot = tid + t * 128;
                int row = slot >> 2, c4 = slot & 3;
                float4 v = *(const float4*)(B + (long)(bn + row) * K + k0 + c4 * 4);
                Bs[c4 * 4 + 0][row] = __uint_as_float(f2tf32(v.x));
                Bs[c4 * 4 + 1][row] = __uint_as_float(f2tf32(v.y));
                Bs[c4 * 4 + 2][row] = __uint_as_float(f2tf32(v.z));
                Bs[c4 * 4 + 3][row] = __uint_as_float(f2tf32(v.w));
            }
        }
        __syncthreads();

#pragma unroll
        for (int ks = 0; ks < 16; ks += 8) {
            unsigned a[2][4], bf[4][2];
#pragma unroll
            for (int mt = 0; mt < 2; mt++) {
                int m = wm + mt * 16 + g;
                a[mt][0] = __float_as_uint(Asp[(ks + tg) * SPAD + m]);
                a[mt][1] = __float_as_uint(Asp[(ks + tg) * SPAD + m + 8]);
                a[mt][2] = __float_as_uint(Asp[(ks + tg + 4) * SPAD + m]);
                a[mt][3] = __float_as_uint(Asp[(ks + tg + 4) * SPAD + m + 8]);
            }
#pragma unroll
            for (int nt = 0; nt < 4; nt++) {
                int n = wn + nt * 8 + g;
                bf[nt][0] = __float_as_uint(Bsp[(ks + tg) * SPAD + n]);
                bf[nt][1] = __float_as_uint(Bsp[(ks + tg + 4) * SPAD + n]);
            }
#pragma unroll
            for (int mt = 0; mt < 2; mt++)
#pragma unroll
                for (int nt = 0; nt < 4; nt++) {
                    asm volatile(
                        "mma.sync.aligned.m16n8k8.row.col.f32.tf32.tf32.f32 "
                        "{%0,%1,%2,%3}, {%4,%5,%6,%7}, {%8,%9}, {%0,%1,%2,%3};\n"
                        : "+f"(acc[mt][nt][0]), "+f"(acc[mt][nt][1]),
                          "+f"(acc[mt][nt][2]), "+f"(acc[mt][nt][3])
                        : "r"(a[mt][0]), "r"(a[mt][1]), "r"(a[mt][2]), "r"(a[mt][3]),
                          "r"(bf[nt][0]), "r"(bf[nt][1]));
                }
        }
        __syncthreads();
    }

    // Epilogue: c0/c1 at (row, 2tg), c2/c3 at (row+8, 2tg)
#pragma unroll
    for (int mt = 0; mt < 2; mt++) {
        int row = bm + wm + mt * 16 + g;
#pragma unroll
        for (int nt = 0; nt < 4; nt++) {
            int col = bn + wn + nt * 8 + tg * 2;
            float2 v0 = make_float2(acc[mt][nt][0] * alpha, acc[mt][nt][1] * alpha);
            float2 v1 = make_float2(acc[mt][nt][2] * alpha, acc[mt][nt][3] * alpha);
            *(float2*)(C + (long)row * N + col)       = v0;
            *(float2*)(C + (long)(row + 8) * N + col) = v1;
        }
    }
}

// ---------------------------------------------------------------------------
// InstanceNorm stats, split across 8 blocks per slice, float atomics.
// g_red must be zero on entry (module init / re-zeroed by stats_fin).
// ---------------------------------------------------------------------------
__global__ __launch_bounds__(256)
void stats_part(const float* __restrict__ attn, int len)
{
    int gidx = blockIdx.x;
    const float4* p = (const float4*)(attn + (long)gidx * len);
    int n4 = len >> 2;
    int per = n4 / gridDim.y;
    int beg = blockIdx.y * per;
    float s = 0.f, s2 = 0.f;
    for (int i = beg + threadIdx.x; i < beg + per; i += 256) {
        float4 v = p[i];
        s += v.x + v.y + v.z + v.w;
        s2 = fmaf(v.x, v.x, fmaf(v.y, v.y, fmaf(v.z, v.z, fmaf(v.w, v.w, s2))));
    }
    __shared__ float sh[16];
#pragma unroll
    for (int o = 16; o > 0; o >>= 1) {
        s  += __shfl_down_sync(0xffffffffu, s,  o);
        s2 += __shfl_down_sync(0xffffffffu, s2, o);
    }
    int w = threadIdx.x >> 5, lane = threadIdx.x & 31;
    if (lane == 0) { sh[w] = s; sh[w + 8] = s2; }
    __syncthreads();
    if (threadIdx.x == 0) {
        float S = 0.f, S2 = 0.f;
        for (int i = 0; i < 8; i++) { S += sh[i]; S2 += sh[i + 8]; }
        atomicAdd(&g_red[2 * gidx],     S);
        atomicAdd(&g_red[2 * gidx + 1], S2);
    }
}

__global__ void stats_fin(int len)
{
    int gidx = threadIdx.x;
    if (gidx < GB) {
        float S = g_red[2 * gidx], S2 = g_red[2 * gidx + 1];
        float mean = S / (float)len;
        float var = S2 / (float)len - mean * mean;
        g_stats[2 * gidx]     = mean;
        g_stats[2 * gidx + 1] = rsqrtf(fmaxf(var, 0.f) + 1e-5f);
        g_red[2 * gidx] = 0.f;          // re-zero for next graph replay
        g_red[2 * gidx + 1] = 0.f;
    }
}

// ---------------------------------------------------------------------------
// Row softmax over 960 with (x - mean) * rstd pre-transform.
// One block (256 threads) per (row c, slice g); one float4 per thread (240 used).
// ---------------------------------------------------------------------------
__global__ __launch_bounds__(256)
void softmax_kernel(float* __restrict__ attn, int C)
{
    long gidx = blockIdx.y;
    long c = blockIdx.x;
    float* row = attn + (gidx * C + c) * SDIM;
    float mean = g_stats[2 * gidx];
    float r    = g_stats[2 * gidx + 1];
    int tid = threadIdx.x;
    int w = tid >> 5, lane = tid & 31;
    bool active = tid < 240;
    __shared__ float sh[8];

    float4 v;
    if (active) {
        v = ((const float4*)row)[tid];
        v.x = (v.x - mean) * r; v.y = (v.y - mean) * r;
        v.z = (v.z - mean) * r; v.w = (v.w - mean) * r;
    } else {
        v = make_float4(-3.0e38f, -3.0e38f, -3.0e38f, -3.0e38f);
    }

    float mx = fmaxf(fmaxf(v.x, v.y), fmaxf(v.z, v.w));
#pragma unroll
    for (int o = 16; o > 0; o >>= 1) mx = fmaxf(mx, __shfl_xor_sync(0xffffffffu, mx, o));
    if (lane == 0) sh[w] = mx;
    __syncthreads();
    if (w == 0) {
        float m2 = (lane < 8) ? sh[lane] : -3.0e38f;
#pragma unroll
        for (int o = 4; o > 0; o >>= 1) m2 = fmaxf(m2, __shfl_xor_sync(0xffffffffu, m2, o));
        if (lane == 0) sh[0] = m2;
    }
    __syncthreads();
    mx = sh[0];
    __syncthreads();

    v.x = __expf(v.x - mx); v.y = __expf(v.y - mx);
    v.z = __expf(v.z - mx); v.w = __expf(v.w - mx);
    float s = v.x + v.y + v.z + v.w;
#pragma unroll
    for (int o = 16; o > 0; o >>= 1) s += __shfl_xor_sync(0xffffffffu, s, o);
    if (lane == 0) sh[w] = s;
    __syncthreads();
    if (w == 0) {
        float t = (lane < 8) ? sh[lane] : 0.f;
#pragma unroll
        for (int o = 4; o > 0; o >>= 1) t += __shfl_xor_sync(0xffffffffu, t, o);
        if (lane == 0) sh[0] = t;
    }
    __syncthreads();
    float inv = 1.f / sh[0];
    if (active) {
        v.x *= inv; v.y *= inv; v.z *= inv; v.w *= inv;
        ((float4*)row)[tid] = v;
    }
}

// ---------------------------------------------------------------------------
// Launch sequence
// ---------------------------------------------------------------------------
extern "C" void kernel_launch(void* const* d_in, const int* in_sizes, int n_in,
                              void* d_out, int out_size)
{
    const float* Q[4]  = { (const float*)d_in[0], (const float*)d_in[1],
                           (const float*)d_in[2], (const float*)d_in[3] };
    const float* KV    = (const float*)d_in[4];
    const float* Wk    = (const float*)d_in[5];
    const float* Wv    = (const float*)d_in[6];
    const float* Wq[4] = { (const float*)d_in[7], (const float*)d_in[8],
                           (const float*)d_in[9], (const float*)d_in[10] };
    const float* Wo[4] = { (const float*)d_in[11], (const float*)d_in[12],
                           (const float*)d_in[13], (const float*)d_in[14] };
    float* out = (float*)d_out;

    float *Kt, *KVt, *Qt, *attn, *outpre;
    cudaGetSymbolAddress((void**)&Kt,     g_Kt);
    cudaGetSymbolAddress((void**)&KVt,    g_KVt);
    cudaGetSymbolAddress((void**)&Qt,     g_Qt);
    cudaGetSymbolAddress((void**)&attn,   g_attn);
    cudaGetSymbolAddress((void**)&outpre, g_outpre);

    const float inv_scale = 1.0f / sqrtf((float)SDIM);

    // KV transform: Kt = KV @ Wk^T ; KVt = Kt @ Wv^T   (per-head weights)
    gemm_tf32<true, false><<<dim3(SDIM / 64, NSEQ / 64, GB), 128>>>(
        KV, Wk, Kt, NSEQ, SDIM, SDIM,
        (long)NSEQ * SDIM, (long)SDIM * SDIM, (long)NSEQ * SDIM, 1.f);
    gemm_tf32<true, false><<<dim3(SDIM / 64, NSEQ / 64, GB), 128>>>(
        Kt, Wv, KVt, NSEQ, SDIM, SDIM,
        (long)NSEQ * SDIM, (long)SDIM * SDIM, (long)NSEQ * SDIM, 1.f);

    const int Cs[4] = { 64, 128, 256, 512 };
    long ooff = 0;
    for (int i = 0; i < 4; i++) {
        const int C = Cs[i];

        // Qt = Qh @ Wq^T : [128, C] per slice
        gemm_tf32<true, false><<<dim3(C / 64, NSEQ / 64, GB), 128>>>(
            Q[i], Wq[i], Qt, NSEQ, C, C,
            (long)NSEQ * C, (long)C * C, (long)NSEQ * C, 1.f);

        // attn[c,s] = inv_scale * sum_n Qt[n,c] * KVt[n,s] : [C, 960]
        gemm_tf32<false, true><<<dim3(SDIM / 64, C / 64, GB), 128>>>(
            Qt, KVt, attn, C, SDIM, NSEQ,
            (long)NSEQ * C, (long)NSEQ * SDIM, (long)C * SDIM, inv_scale);

        // InstanceNorm stats + softmax over s
        stats_part<<<dim3(GB, 8), 256>>>(attn, C * SDIM);
        stats_fin<<<1, GB>>>(C * SDIM);
        softmax_kernel<<<dim3(C, GB), 256>>>(attn, C);

        // outpre[n,c] = sum_s KVt[n,s] * attn[c,s] : [128, C] per slice
        gemm_tf32<false, false><<<dim3(C / 64, NSEQ / 64, GB), 128>>>(
            KVt, attn, outpre, NSEQ, C, SDIM,
            (long)NSEQ * SDIM, (long)C * SDIM, (long)NSEQ * C, 1.f);

        // Y = outpre @ Wo^T : [8192, C]
        gemm_tf32<false, false><<<dim3(C / 64, 8192 / 64, 1), 128>>>(
            outpre, Wo[i], out + ooff, 8192, C, C, 0, 0, 0, 1.f);

        ooff += 8192L * C;
    }
}

// round 6
// speedup vs baseline: 2.6871x; 1.5720x over previous
#include <cuda_runtime.h>
#include <cstdint>
#include <math.h>

// Problem constants
#define GB 64        // B*H batched slices
#define NSEQ 128     // tokens per head
#define SDIM 960     // K/V feature dim
#define BK 32
#define BN 64

// Scratch (device globals; no allocation allowed)
__device__ float g_Kt[GB * NSEQ * SDIM];
__device__ float g_KVt[GB * NSEQ * SDIM];
__device__ float g_Qt[GB * NSEQ * 512];
__device__ float g_attn[GB * 512 * SDIM];
__device__ float g_outpre[8192 * 512];
__device__ float g_stats[GB * 2];
__device__ float g_red[GB * 2];

__device__ __forceinline__ unsigned f2tf32(float x) {
    unsigned u;
    asm("cvt.rna.tf32.f32 %0, %1;" : "=r"(u) : "f"(x));
    return u;
}

__device__ __forceinline__ void cpa16(unsigned int dst, const float* src) {
    asm volatile("cp.async.cg.shared.global [%0], [%1], 16;\n" :: "r"(dst), "l"(src));
}

// ---------------------------------------------------------------------------
// Pipelined TF32 GEMM. C[m,n] = alpha * sum_k a(m,k) * b(n,k)
// AT: A global is KxM row-major (k-major); else MxK row-major.
// BT: B global is KxN row-major; else NxK row-major.
// BM in {64,128}, BN=64, BK=32, 256 threads, cp.async double buffer.
// M div by BM, N div by 64, K div by 32.
// ---------------------------------------------------------------------------
template<int BM, bool MODB, bool AT, bool BT>
__global__ __launch_bounds__(256)
void gemm_pipe(const float* __restrict__ Ab, const float* __restrict__ Bb,
               float* __restrict__ Cb, int M, int N, int K,
               long sA, long sB, long sC, float alpha)
{
    constexpr int SA = AT ? (BM + 8) : (BK + 4);   // row stride (floats)
    constexpr int SB = BT ? (BN + 8) : (BK + 4);
    constexpr int ASZ = AT ? BK * SA : BM * SA;
    constexpr int BSZ = BT ? BK * SB : BN * SB;
    constexpr int NT = (BM == 128) ? 4 : 2;        // 8-wide mma tiles per warp (n)

    extern __shared__ float sm[];
    float* As = sm;               // [2][ASZ]
    float* Bs = sm + 2 * ASZ;     // [2][BSZ]
    const unsigned int sA_u32 = (unsigned int)__cvta_generic_to_shared(As);
    const unsigned int sB_u32 = (unsigned int)__cvta_generic_to_shared(Bs);

    const int b = blockIdx.z;
    const float* A = Ab + (long)b * sA;
    const float* B = Bb + (MODB ? (long)(b & 7) : (long)b) * sB;
    float* C = Cb + (long)b * sC;

    const int bm = blockIdx.y * BM;
    const int bn = blockIdx.x * BN;
    const int tid = threadIdx.x;
    const int warp = tid >> 5, lane = tid & 31;
    const int g = lane >> 2, tg = lane & 3;
    const int wm = (BM == 128) ? (warp & 3) * 32 : (warp & 1) * 32;
    const int wn = (BM == 128) ? (warp >> 2) * 32 : (warp >> 1) * 16;

    float acc[2][NT][4];
#pragma unroll
    for (int i = 0; i < 2; i++)
#pragma unroll
        for (int j = 0; j < NT; j++)
#pragma unroll
            for (int c = 0; c < 4; c++) acc[i][j][c] = 0.f;

    // ---- async tile loaders --------------------------------------------
    auto load_tiles = [&](int stage, int k0) {
        // A tile
        if (AT) {
            constexpr int CH = BM / 4;          // float4 per k-row
            constexpr int TOT = BK * CH;
#pragma unroll
            for (int t = 0; t < TOT / 256; t++) {
                int slot = tid + t * 256;
                int kk = slot / CH, m4 = slot % CH;
                cpa16(sA_u32 + (stage * ASZ + kk * SA + m4 * 4) * 4,
                      A + (long)(k0 + kk) * M + bm + m4 * 4);
            }
        } else {
            constexpr int CH = BK / 4;          // 8 float4 per m-row
            constexpr int TOT = BM * CH;
#pragma unroll
            for (int t = 0; t < TOT / 256; t++) {
                int slot = tid + t * 256;
                int m = slot / CH, c4 = slot % CH;
                cpa16(sA_u32 + (stage * ASZ + m * SA + c4 * 4) * 4,
                      A + (long)(bm + m) * K + k0 + c4 * 4);
            }
        }
        // B tile
        if (BT) {
            constexpr int CH = BN / 4;
#pragma unroll
            for (int t = 0; t < (BK * CH) / 256; t++) {
                int slot = tid + t * 256;
                int kk = slot / CH, n4 = slot % CH;
                cpa16(sB_u32 + (stage * BSZ + kk * SB + n4 * 4) * 4,
                      B + (long)(k0 + kk) * N + bn + n4 * 4);
            }
        } else {
            constexpr int CH = BK / 4;
#pragma unroll
            for (int t = 0; t < (BN * CH) / 256; t++) {
                int slot = tid + t * 256;
                int n = slot / CH, c4 = slot % CH;
                cpa16(sB_u32 + (stage * BSZ + n * SB + c4 * 4) * 4,
                      B + (long)(bn + n) * K + k0 + c4 * 4);
            }
        }
        asm volatile("cp.async.commit_group;\n");
    };

    const int T = K / BK;
    load_tiles(0, 0);

    for (int t = 0; t < T; t++) {
        if (t + 1 < T) {
            load_tiles((t + 1) & 1, (t + 1) * BK);
            asm volatile("cp.async.wait_group 1;\n");
        } else {
            asm volatile("cp.async.wait_group 0;\n");
        }
        __syncthreads();

        const float* Ast = As + (t & 1) * ASZ;
        const float* Bst = Bs + (t & 1) * BSZ;
#pragma unroll
        for (int ks = 0; ks < BK; ks += 8) {
            unsigned a[2][4], bf[NT][2];
#pragma unroll
            for (int mt = 0; mt < 2; mt++) {
                int m = wm + mt * 16 + g;
                if (AT) {
                    a[mt][0] = f2tf32(Ast[(ks + tg) * SA + m]);
                    a[mt][1] = f2tf32(Ast[(ks + tg) * SA + m + 8]);
                    a[mt][2] = f2tf32(Ast[(ks + tg + 4) * SA + m]);
                    a[mt][3] = f2tf32(Ast[(ks + tg + 4) * SA + m + 8]);
                } else {
                    a[mt][0] = f2tf32(Ast[m * SA + ks + tg]);
                    a[mt][1] = f2tf32(Ast[(m + 8) * SA + ks + tg]);
                    a[mt][2] = f2tf32(Ast[m * SA + ks + tg + 4]);
                    a[mt][3] = f2tf32(Ast[(m + 8) * SA + ks + tg + 4]);
                }
            }
#pragma unroll
            for (int nt = 0; nt < NT; nt++) {
                int n = wn + nt * 8 + g;
                if (BT) {
                    bf[nt][0] = f2tf32(Bst[(ks + tg) * SB + n]);
                    bf[nt][1] = f2tf32(Bst[(ks + tg + 4) * SB + n]);
                } else {
                    bf[nt][0] = f2tf32(Bst[n * SB + ks + tg]);
                    bf[nt][1] = f2tf32(Bst[n * SB + ks + tg + 4]);
                }
            }
#pragma unroll
            for (int mt = 0; mt < 2; mt++)
#pragma unroll
                for (int nt = 0; nt < NT; nt++) {
                    asm volatile(
                        "mma.sync.aligned.m16n8k8.row.col.f32.tf32.tf32.f32 "
                        "{%0,%1,%2,%3}, {%4,%5,%6,%7}, {%8,%9}, {%0,%1,%2,%3};\n"
                        : "+f"(acc[mt][nt][0]), "+f"(acc[mt][nt][1]),
                          "+f"(acc[mt][nt][2]), "+f"(acc[mt][nt][3])
                        : "r"(a[mt][0]), "r"(a[mt][1]), "r"(a[mt][2]), "r"(a[mt][3]),
                          "r"(bf[nt][0]), "r"(bf[nt][1]));
                }
        }
        __syncthreads();
    }

#pragma unroll
    for (int mt = 0; mt < 2; mt++) {
        int row = bm + wm + mt * 16 + g;
#pragma unroll
        for (int nt = 0; nt < NT; nt++) {
            int col = bn + wn + nt * 8 + tg * 2;
            float2 v0 = make_float2(acc[mt][nt][0] * alpha, acc[mt][nt][1] * alpha);
            float2 v1 = make_float2(acc[mt][nt][2] * alpha, acc[mt][nt][3] * alpha);
            *(float2*)(C + (long)row * N + col)       = v0;
            *(float2*)(C + (long)(row + 8) * N + col) = v1;
        }
    }
}

// ---------------------------------------------------------------------------
// InstanceNorm stats (split reduction, self-zeroing atomics)
// ---------------------------------------------------------------------------
__global__ __launch_bounds__(256)
void stats_part(const float* __restrict__ attn, int len)
{
    int gidx = blockIdx.x;
    const float4* p = (const float4*)(attn + (long)gidx * len);
    int n4 = len >> 2;
    int per = n4 / gridDim.y;
    int beg = blockIdx.y * per;
    float s = 0.f, s2 = 0.f;
    for (int i = beg + threadIdx.x; i < beg + per; i += 256) {
        float4 v = p[i];
        s += v.x + v.y + v.z + v.w;
        s2 = fmaf(v.x, v.x, fmaf(v.y, v.y, fmaf(v.z, v.z, fmaf(v.w, v.w, s2))));
    }
    __shared__ float sh[16];
#pragma unroll
    for (int o = 16; o > 0; o >>= 1) {
        s  += __shfl_down_sync(0xffffffffu, s,  o);
        s2 += __shfl_down_sync(0xffffffffu, s2, o);
    }
    int w = threadIdx.x >> 5, lane = threadIdx.x & 31;
    if (lane == 0) { sh[w] = s; sh[w + 8] = s2; }
    __syncthreads();
    if (threadIdx.x == 0) {
        float S = 0.f, S2 = 0.f;
        for (int i = 0; i < 8; i++) { S += sh[i]; S2 += sh[i + 8]; }
        atomicAdd(&g_red[2 * gidx],     S);
        atomicAdd(&g_red[2 * gidx + 1], S2);
    }
}

__global__ void stats_fin(int len)
{
    int gidx = threadIdx.x;
    if (gidx < GB) {
        float S = g_red[2 * gidx], S2 = g_red[2 * gidx + 1];
        float mean = S / (float)len;
        float var = S2 / (float)len - mean * mean;
        g_stats[2 * gidx]     = mean;
        g_stats[2 * gidx + 1] = rsqrtf(fmaxf(var, 0.f) + 1e-5f);
        g_red[2 * gidx] = 0.f;
        g_red[2 * gidx + 1] = 0.f;
    }
}

// ---------------------------------------------------------------------------
// Row softmax over 960 with (x - mean) * rstd pre-transform.
// ---------------------------------------------------------------------------
__global__ __launch_bounds__(256)
void softmax_kernel(float* __restrict__ attn, int C)
{
    long gidx = blockIdx.y;
    long c = blockIdx.x;
    float* row = attn + (gidx * C + c) * SDIM;
    float mean = g_stats[2 * gidx];
    float r    = g_stats[2 * gidx + 1];
    int tid = threadIdx.x;
    int w = tid >> 5, lane = tid & 31;
    bool active = tid < 240;
    __shared__ float sh[8];

    float4 v;
    if (active) {
        v = ((const float4*)row)[tid];
        v.x = (v.x - mean) * r; v.y = (v.y - mean) * r;
        v.z = (v.z - mean) * r; v.w = (v.w - mean) * r;
    } else {
        v = make_float4(-3.0e38f, -3.0e38f, -3.0e38f, -3.0e38f);
    }

    float mx = fmaxf(fmaxf(v.x, v.y), fmaxf(v.z, v.w));
#pragma unroll
    for (int o = 16; o > 0; o >>= 1) mx = fmaxf(mx, __shfl_xor_sync(0xffffffffu, mx, o));
    if (lane == 0) sh[w] = mx;
    __syncthreads();
    if (w == 0) {
        float m2 = (lane < 8) ? sh[lane] : -3.0e38f;
#pragma unroll
        for (int o = 4; o > 0; o >>= 1) m2 = fmaxf(m2, __shfl_xor_sync(0xffffffffu, m2, o));
        if (lane == 0) sh[0] = m2;
    }
    __syncthreads();
    mx = sh[0];
    __syncthreads();

    v.x = __expf(v.x - mx); v.y = __expf(v.y - mx);
    v.z = __expf(v.z - mx); v.w = __expf(v.w - mx);
    float s = v.x + v.y + v.z + v.w;
#pragma unroll
    for (int o = 16; o > 0; o >>= 1) s += __shfl_xor_sync(0xffffffffu, s, o);
    if (lane == 0) sh[w] = s;
    __syncthreads();
    if (w == 0) {
        float t = (lane < 8) ? sh[lane] : 0.f;
#pragma unroll
        for (int o = 4; o > 0; o >>= 1) t += __shfl_xor_sync(0xffffffffu, t, o);
        if (lane == 0) sh[0] = t;
    }
    __syncthreads();
    float inv = 1.f / sh[0];
    if (active) {
        v.x *= inv; v.y *= inv; v.z *= inv; v.w *= inv;
        ((float4*)row)[tid] = v;
    }
}

// ---------------------------------------------------------------------------
// Launch sequence
// ---------------------------------------------------------------------------
static inline int smem_bytes(int ASZ, int BSZ) { return (2 * (ASZ + BSZ)) * 4; }

extern "C" void kernel_launch(void* const* d_in, const int* in_sizes, int n_in,
                              void* d_out, int out_size)
{
    const float* Q[4]  = { (const float*)d_in[0], (const float*)d_in[1],
                           (const float*)d_in[2], (const float*)d_in[3] };
    const float* KV    = (const float*)d_in[4];
    const float* Wk    = (const float*)d_in[5];
    const float* Wv    = (const float*)d_in[6];
    const float* Wq[4] = { (const float*)d_in[7], (const float*)d_in[8],
                           (const float*)d_in[9], (const float*)d_in[10] };
    const float* Wo[4] = { (const float*)d_in[11], (const float*)d_in[12],
                           (const float*)d_in[13], (const float*)d_in[14] };
    float* out = (float*)d_out;

    float *Kt, *KVt, *Qt, *attn, *outpre;
    cudaGetSymbolAddress((void**)&Kt,     g_Kt);
    cudaGetSymbolAddress((void**)&KVt,    g_KVt);
    cudaGetSymbolAddress((void**)&Qt,     g_Qt);
    cudaGetSymbolAddress((void**)&attn,   g_attn);
    cudaGetSymbolAddress((void**)&outpre, g_outpre);

    // smem sizes per instantiation
    const int SM_NN   = smem_bytes(128 * 36, 64 * 36);       // <128,*,F,F>
    const int SM_TT   = smem_bytes(32 * 136, 32 * 72);       // <128,F,T,T>
    const int SM_TT64 = smem_bytes(32 * 72, 32 * 72);        // <64,F,T,T>

    cudaFuncSetAttribute(gemm_pipe<128, true,  false, false>,
                         cudaFuncAttributeMaxDynamicSharedMemorySize, SM_NN);
    cudaFuncSetAttribute(gemm_pipe<128, false, false, false>,
                         cudaFuncAttributeMaxDynamicSharedMemorySize, SM_NN);
    cudaFuncSetAttribute(gemm_pipe<128, false, true, true>,
                         cudaFuncAttributeMaxDynamicSharedMemorySize, SM_TT);
    cudaFuncSetAttribute(gemm_pipe<64, false, true, true>,
                         cudaFuncAttributeMaxDynamicSharedMemorySize, SM_TT64);

    const float inv_scale = 1.0f / sqrtf((float)SDIM);

    // KV transform: Kt = KV @ Wk^T ; KVt = Kt @ Wv^T (per-head weights)
    gemm_pipe<128, true, false, false><<<dim3(SDIM / 64, 1, GB), 256, SM_NN>>>(
        KV, Wk, Kt, NSEQ, SDIM, SDIM,
        (long)NSEQ * SDIM, (long)SDIM * SDIM, (long)NSEQ * SDIM, 1.f);
    gemm_pipe<128, true, false, false><<<dim3(SDIM / 64, 1, GB), 256, SM_NN>>>(
        Kt, Wv, KVt, NSEQ, SDIM, SDIM,
        (long)NSEQ * SDIM, (long)SDIM * SDIM, (long)NSEQ * SDIM, 1.f);

    const int Cs[4] = { 64, 128, 256, 512 };
    long ooff = 0;
    for (int i = 0; i < 4; i++) {
        const int C = Cs[i];

        // Qt = Qh @ Wq^T : [128, C] per slice
        gemm_pipe<128, true, false, false><<<dim3(C / 64, 1, GB), 256, SM_NN>>>(
            Q[i], Wq[i], Qt, NSEQ, C, C,
            (long)NSEQ * C, (long)C * C, (long)NSEQ * C, 1.f);

        // attn[c,s] = inv_scale * sum_n Qt[n,c] * KVt[n,s] : [C, 960]
        if (C == 64) {
            gemm_pipe<64, false, true, true><<<dim3(SDIM / 64, 1, GB), 256, SM_TT64>>>(
                Qt, KVt, attn, C, SDIM, NSEQ,
                (long)NSEQ * C, (long)NSEQ * SDIM, (long)C * SDIM, inv_scale);
        } else {
            gemm_pipe<128, false, true, true><<<dim3(SDIM / 64, C / 128, GB), 256, SM_TT>>>(
                Qt, KVt, attn, C, SDIM, NSEQ,
                (long)NSEQ * C, (long)NSEQ * SDIM, (long)C * SDIM, inv_scale);
        }

        // InstanceNorm stats + softmax over s
        stats_part<<<dim3(GB, 16), 256>>>(attn, C * SDIM);
        stats_fin<<<1, GB>>>(C * SDIM);
        softmax_kernel<<<dim3(C, GB), 256>>>(attn, C);

        // outpre[n,c] = sum_s KVt[n,s] * attn[c,s] : [128, C] per slice
        gemm_pipe<128, false, false, false><<<dim3(C / 64, 1, GB), 256, SM_NN>>>(
            KVt, attn, outpre, NSEQ, C, SDIM,
            (long)NSEQ * SDIM, (long)C * SDIM, (long)NSEQ * C, 1.f);

        // Y = outpre @ Wo^T : [8192, C]
        gemm_pipe<128, false, false, false><<<dim3(C / 64, 8192 / 128, 1), 256, SM_NN>>>(
            outpre, Wo[i], out + ooff, 8192, C, C, 0, 0, 0, 1.f);

        ooff += 8192L * C;
    }
}

// round 10
// speedup vs baseline: 2.8222x; 1.0503x over previous
#include <cuda_runtime.h>
#include <cstdint>
#include <math.h>

// Problem constants
#define GB 64        // B*H batched slices
#define NSEQ 128     // tokens per head
#define SDIM 960     // K/V feature dim
#define BK 32
#define BN 64

// Scratch (device globals; no allocation allowed)
__device__ float g_Kt[GB * NSEQ * SDIM];
__device__ float g_KVt[GB * NSEQ * SDIM];
__device__ float g_Qt[GB * NSEQ * 512];
__device__ float g_attn[GB * 512 * SDIM];
__device__ float g_outpre[8192 * 512];
__device__ float g_stats[GB * 2];           // mean, rstd per slice
__device__ float g_red[GB * 2];             // atomic sum / sumsq (self-zeroing)
__device__ unsigned g_rowmax_u[GB * 512];   // ordered-uint row max (per branch)

__device__ __forceinline__ unsigned f2tf32(float x) {
    unsigned u;
    asm("cvt.rna.tf32.f32 %0, %1;" : "=r"(u) : "f"(x));
    return u;
}

__device__ __forceinline__ void cpa16(unsigned int dst, const float* src) {
    asm volatile("cp.async.cg.shared.global [%0], [%1], 16;\n" :: "r"(dst), "l"(src));
}

// ordered-uint encode/decode for float atomicMax
__device__ __forceinline__ unsigned fenc(float x) {
    unsigned u = __float_as_uint(x);
    return (u & 0x80000000u) ? ~u : (u | 0x80000000u);
}
__device__ __forceinline__ float fdec(unsigned u) {
    return (u & 0x80000000u) ? __uint_as_float(u & 0x7fffffffu)
                             : __uint_as_float(~u);
}

// ---------------------------------------------------------------------------
// Pipelined TF32 GEMM. C[m,n] = alpha * sum_k a(m,k) * b(n,k)
// AT: A global KxM row-major; else MxK. BT: B global KxN row-major; else NxK.
// EPI: logits epilogue — accumulate per-slice sum/sumsq (g_red) and per-row
//      raw max (g_rowmax_u[b*M + row]) of the scaled outputs.
// ---------------------------------------------------------------------------
template<int BM, bool MODB, bool AT, bool BT, bool EPI>
__global__ __launch_bounds__(256)
void gemm_pipe(const float* __restrict__ Ab, const float* __restrict__ Bb,
               float* __restrict__ Cb, int M, int N, int K,
               long sA, long sB, long sC, float alpha)
{
    constexpr int SA = AT ? (BM + 8) : (BK + 4);
    constexpr int SB = BT ? (BN + 8) : (BK + 4);
    constexpr int ASZ = AT ? BK * SA : BM * SA;
    constexpr int BSZ = BT ? BK * SB : BN * SB;
    constexpr int NT = (BM == 128) ? 4 : 2;

    extern __shared__ float sm[];
    float* As = sm;
    float* Bs = sm + 2 * ASZ;
    const unsigned int sA_u32 = (unsigned int)__cvta_generic_to_shared(As);
    const unsigned int sB_u32 = (unsigned int)__cvta_generic_to_shared(Bs);

    const int b = blockIdx.z;
    const float* A = Ab + (long)b * sA;
    const float* B = Bb + (MODB ? (long)(b & 7) : (long)b) * sB;
    float* C = Cb + (long)b * sC;

    const int bm = blockIdx.y * BM;
    const int bn = blockIdx.x * BN;
    const int tid = threadIdx.x;
    const int warp = tid >> 5, lane = tid & 31;
    const int g = lane >> 2, tg = lane & 3;
    const int wm = (BM == 128) ? (warp & 3) * 32 : (warp & 1) * 32;
    const int wn = (BM == 128) ? (warp >> 2) * 32 : (warp >> 1) * 16;

    float acc[2][NT][4];
#pragma unroll
    for (int i = 0; i < 2; i++)
#pragma unroll
        for (int j = 0; j < NT; j++)
#pragma unroll
            for (int c = 0; c < 4; c++) acc[i][j][c] = 0.f;

    auto load_tiles = [&](int stage, int k0) {
        if (AT) {
            constexpr int CH = BM / 4;
#pragma unroll
            for (int t = 0; t < (BK * CH) / 256; t++) {
                int slot = tid + t * 256;
                int kk = slot / CH, m4 = slot % CH;
                cpa16(sA_u32 + (stage * ASZ + kk * SA + m4 * 4) * 4,
                      A + (long)(k0 + kk) * M + bm + m4 * 4);
            }
        } else {
            constexpr int CH = BK / 4;
#pragma unroll
            for (int t = 0; t < (BM * CH) / 256; t++) {
                int slot = tid + t * 256;
                int m = slot / CH, c4 = slot % CH;
                cpa16(sA_u32 + (stage * ASZ + m * SA + c4 * 4) * 4,
                      A + (long)(bm + m) * K + k0 + c4 * 4);
            }
        }
        if (BT) {
            constexpr int CH = BN / 4;
#pragma unroll
            for (int t = 0; t < (BK * CH) / 256; t++) {
                int slot = tid + t * 256;
                int kk = slot / CH, n4 = slot % CH;
                cpa16(sB_u32 + (stage * BSZ + kk * SB + n4 * 4) * 4,
                      B + (long)(k0 + kk) * N + bn + n4 * 4);
            }
        } else {
            constexpr int CH = BK / 4;
#pragma unroll
            for (int t = 0; t < (BN * CH) / 256; t++) {
                int slot = tid + t * 256;
                int n = slot / CH, c4 = slot % CH;
                cpa16(sB_u32 + (stage * BSZ + n * SB + c4 * 4) * 4,
                      B + (long)(bn + n) * K + k0 + c4 * 4);
            }
        }
        asm volatile("cp.async.commit_group;\n");
    };

    const int T = K / BK;
    load_tiles(0, 0);

    for (int t = 0; t < T; t++) {
        if (t + 1 < T) {
            load_tiles((t + 1) & 1, (t + 1) * BK);
            asm volatile("cp.async.wait_group 1;\n");
        } else {
            asm volatile("cp.async.wait_group 0;\n");
        }
        __syncthreads();

        const float* Ast = As + (t & 1) * ASZ;
        const float* Bst = Bs + (t & 1) * BSZ;
#pragma unroll
        for (int ks = 0; ks < BK; ks += 8) {
            unsigned a[2][4], bf[NT][2];
#pragma unroll
            for (int mt = 0; mt < 2; mt++) {
                int m = wm + mt * 16 + g;
                if (AT) {
                    a[mt][0] = f2tf32(Ast[(ks + tg) * SA + m]);
                    a[mt][1] = f2tf32(Ast[(ks + tg) * SA + m + 8]);
                    a[mt][2] = f2tf32(Ast[(ks + tg + 4) * SA + m]);
                    a[mt][3] = f2tf32(Ast[(ks + tg + 4) * SA + m + 8]);
                } else {
                    a[mt][0] = f2tf32(Ast[m * SA + ks + tg]);
                    a[mt][1] = f2tf32(Ast[(m + 8) * SA + ks + tg]);
                    a[mt][2] = f2tf32(Ast[m * SA + ks + tg + 4]);
                    a[mt][3] = f2tf32(Ast[(m + 8) * SA + ks + tg + 4]);
                }
            }
#pragma unroll
            for (int nt = 0; nt < NT; nt++) {
                int n = wn + nt * 8 + g;
                if (BT) {
                    bf[nt][0] = f2tf32(Bst[(ks + tg) * SB + n]);
                    bf[nt][1] = f2tf32(Bst[(ks + tg + 4) * SB + n]);
                } else {
                    bf[nt][0] = f2tf32(Bst[n * SB + ks + tg]);
                    bf[nt][1] = f2tf32(Bst[n * SB + ks + tg + 4]);
                }
            }
#pragma unroll
            for (int mt = 0; mt < 2; mt++)
#pragma unroll
                for (int nt = 0; nt < NT; nt++) {
                    asm volatile(
                        "mma.sync.aligned.m16n8k8.row.col.f32.tf32.tf32.f32 "
                        "{%0,%1,%2,%3}, {%4,%5,%6,%7}, {%8,%9}, {%0,%1,%2,%3};\n"
                        : "+f"(acc[mt][nt][0]), "+f"(acc[mt][nt][1]),
                          "+f"(acc[mt][nt][2]), "+f"(acc[mt][nt][3])
                        : "r"(a[mt][0]), "r"(a[mt][1]), "r"(a[mt][2]), "r"(a[mt][3]),
                          "r"(bf[nt][0]), "r"(bf[nt][1]));
                }
        }
        __syncthreads();
    }

    float psum = 0.f, psq = 0.f;
#pragma unroll
    for (int mt = 0; mt < 2; mt++) {
        int row = bm + wm + mt * 16 + g;
        float r0m = -3.0e38f, r1m = -3.0e38f;
#pragma unroll
        for (int nt = 0; nt < NT; nt++) {
            int col = bn + wn + nt * 8 + tg * 2;
            float2 v0 = make_float2(acc[mt][nt][0] * alpha, acc[mt][nt][1] * alpha);
            float2 v1 = make_float2(acc[mt][nt][2] * alpha, acc[mt][nt][3] * alpha);
            *(float2*)(C + (long)row * N + col)       = v0;
            *(float2*)(C + (long)(row + 8) * N + col) = v1;
            if (EPI) {
                psum += v0.x + v0.y + v1.x + v1.y;
                psq = fmaf(v0.x, v0.x, fmaf(v0.y, v0.y,
                      fmaf(v1.x, v1.x, fmaf(v1.y, v1.y, psq))));
                r0m = fmaxf(r0m, fmaxf(v0.x, v0.y));
                r1m = fmaxf(r1m, fmaxf(v1.x, v1.y));
            }
        }
        if (EPI) {
            atomicMax(&g_rowmax_u[(long)b * M + row],     fenc(r0m));
            atomicMax(&g_rowmax_u[(long)b * M + row + 8], fenc(r1m));
        }
    }

    if (EPI) {
        __shared__ float red_sh[16];
#pragma unroll
        for (int o = 16; o > 0; o >>= 1) {
            psum += __shfl_down_sync(0xffffffffu, psum, o);
            psq  += __shfl_down_sync(0xffffffffu, psq,  o);
        }
        if (lane == 0) { red_sh[warp] = psum; red_sh[warp + 8] = psq; }
        __syncthreads();
        if (tid == 0) {
            float S = 0.f, S2 = 0.f;
            for (int i = 0; i < 8; i++) { S += red_sh[i]; S2 += red_sh[i + 8]; }
            atomicAdd(&g_red[2 * b],     S);
            atomicAdd(&g_red[2 * b + 1], S2);
        }
    }
}

// ---------------------------------------------------------------------------
// AV GEMM with fused softmax. outpre[m, n] = sum_k A[m,k] * p(n,k) / Z_n
// A = KVt (MxK row-major, M=128, K=960), Braw = attn (NxK row-major, N=C cols).
// p = exp((x - rawmax_row) * rstd); Z accumulated per block (block covers all K).
// BM=128, BN=64, 256 threads.
// ---------------------------------------------------------------------------
__global__ __launch_bounds__(256)
void gemm_av(const float* __restrict__ Ab, const float* __restrict__ Bb,
             float* __restrict__ Cb, int N, long sA, long sB, long sC)
{
    constexpr int BM = 128;
    constexpr int SA = BK + 4;
    constexpr int SB = BK + 4;
    constexpr int ASZ = BM * SA;
    constexpr int BSZ = BN * SB;
    constexpr int K = SDIM;

    extern __shared__ float sm[];
    float* As = sm;
    float* Bs = sm + 2 * ASZ;
    float* Zsh   = sm + 2 * ASZ + 2 * BSZ;   // [64]
    float* Rmx   = Zsh + 64;                 // [64]
    const unsigned int sA_u32 = (unsigned int)__cvta_generic_to_shared(As);
    const unsigned int sB_u32 = (unsigned int)__cvta_generic_to_shared(Bs);

    const int b = blockIdx.z;
    const float* A = Ab + (long)b * sA;
    const float* B = Bb + (long)b * sB;
    float* C = Cb + (long)b * sC;

    const int bn = blockIdx.x * BN;
    const int tid = threadIdx.x;
    const int warp = tid >> 5, lane = tid & 31;
    const int g = lane >> 2, tg = lane & 3;
    const int wm = (warp & 3) * 32;
    const int wn = (warp >> 2) * 32;
    const float rstd = g_stats[2 * b + 1];

    if (tid < 64) {
        Zsh[tid] = 0.f;
        Rmx[tid] = fdec(g_rowmax_u[(long)b * N + bn + tid]);
    }

    float acc[2][4][4];
#pragma unroll
    for (int i = 0; i < 2; i++)
#pragma unroll
        for (int j = 0; j < 4; j++)
#pragma unroll
            for (int c = 0; c < 4; c++) acc[i][j][c] = 0.f;

    auto load_tiles = [&](int stage, int k0) {
#pragma unroll
        for (int t = 0; t < 4; t++) {               // A: 128 rows x 8 f4
            int slot = tid + t * 256;
            int m = slot >> 3, c4 = slot & 7;
            cpa16(sA_u32 + (stage * ASZ + m * SA + c4 * 4) * 4,
                  A + (long)m * K + k0 + c4 * 4);
        }
#pragma unroll
        for (int t = 0; t < 2; t++) {               // B: 64 rows x 8 f4
            int slot = tid + t * 256;
            int n = slot >> 3, c4 = slot & 7;
            cpa16(sB_u32 + (stage * BSZ + n * SB + c4 * 4) * 4,
                  B + (long)(bn + n) * K + k0 + c4 * 4);
        }
        asm volatile("cp.async.commit_group;\n");
    };

    const int T = K / BK;
    load_tiles(0, 0);

    for (int t = 0; t < T; t++) {
        if (t + 1 < T) {
            load_tiles((t + 1) & 1, (t + 1) * BK);
            asm volatile("cp.async.wait_group 1;\n");
        } else {
            asm volatile("cp.async.wait_group 0;\n");
        }
        __syncthreads();

        float* Bst = Bs + (t & 1) * BSZ;
        // transform: p = exp((x - rawmax) * rstd), accumulate Z
        {
            int n = tid >> 2;                 // 0..63
            int k0 = (tid & 3) * 8;
            float rm = Rmx[n];
            float* p = Bst + n * SB + k0;
            float4 v0 = *(float4*)p;
            float4 v1 = *(float4*)(p + 4);
            v0.x = __expf((v0.x - rm) * rstd); v0.y = __expf((v0.y - rm) * rstd);
            v0.z = __expf((v0.z - rm) * rstd); v0.w = __expf((v0.w - rm) * rstd);
            v1.x = __expf((v1.x - rm) * rstd); v1.y = __expf((v1.y - rm) * rstd);
            v1.z = __expf((v1.z - rm) * rstd); v1.w = __expf((v1.w - rm) * rstd);
            *(float4*)p = v0;
            *(float4*)(p + 4) = v1;
            float part = v0.x + v0.y + v0.z + v0.w + v1.x + v1.y + v1.z + v1.w;
            part += __shfl_down_sync(0xffffffffu, part, 2);
            part += __shfl_down_sync(0xffffffffu, part, 1);
            if ((lane & 3) == 0) atomicAdd(&Zsh[n], part);
        }
        __syncthreads();

        const float* Ast = As + (t & 1) * ASZ;
#pragma unroll
        for (int ks = 0; ks < BK; ks += 8) {
            unsigned a[2][4], bf[4][2];
#pragma unroll
            for (int mt = 0; mt < 2; mt++) {
                int m = wm + mt * 16 + g;
                a[mt][0] = f2tf32(Ast[m * SA + ks + tg]);
                a[mt][1] = f2tf32(Ast[(m + 8) * SA + ks + tg]);
                a[mt][2] = f2tf32(Ast[m * SA + ks + tg + 4]);
                a[mt][3] = f2tf32(Ast[(m + 8) * SA + ks + tg + 4]);
            }
#pragma unroll
            for (int nt = 0; nt < 4; nt++) {
                int n = wn + nt * 8 + g;
                bf[nt][0] = f2tf32(Bst[n * SB + ks + tg]);
                bf[nt][1] = f2tf32(Bst[n * SB + ks + tg + 4]);
            }
#pragma unroll
            for (int mt = 0; mt < 2; mt++)
#pragma unroll
                for (int nt = 0; nt < 4; nt++) {
                    asm volatile(
                        "mma.sync.aligned.m16n8k8.row.col.f32.tf32.tf32.f32 "
                        "{%0,%1,%2,%3}, {%4,%5,%6,%7}, {%8,%9}, {%0,%1,%2,%3};\n"
                        : "+f"(acc[mt][nt][0]), "+f"(acc[mt][nt][1]),
                          "+f"(acc[mt][nt][2]), "+f"(acc[mt][nt][3])
                        : "r"(a[mt][0]), "r"(a[mt][1]), "r"(a[mt][2]), "r"(a[mt][3]),
                          "r"(bf[nt][0]), "r"(bf[nt][1]));
                }
        }
        __syncthreads();
    }

#pragma unroll
    for (int mt = 0; mt < 2; mt++) {
        int row = wm + mt * 16 + g;
#pragma unroll
        for (int nt = 0; nt < 4; nt++) {
            int cl = wn + nt * 8 + tg * 2;       // local col
            float iz0 = 1.f / Zsh[cl], iz1 = 1.f / Zsh[cl + 1];
            int col = bn + cl;
            float2 v0 = make_float2(acc[mt][nt][0] * iz0, acc[mt][nt][1] * iz1);
            float2 v1 = make_float2(acc[mt][nt][2] * iz0, acc[mt][nt][3] * iz1);
            *(float2*)(C + (long)row * N + col)       = v0;
            *(float2*)(C + (long)(row + 8) * N + col) = v1;
        }
    }
}

// ---------------------------------------------------------------------------
// finalize: per-slice rstd from sums; re-zero accumulators for graph replay.
// reset_rowmax: clear per-row maxima (encoded min = 0).
// ---------------------------------------------------------------------------
__global__ void stats_fin(int len)
{
    int gidx = threadIdx.x;
    if (gidx < GB) {
        float S = g_red[2 * gidx], S2 = g_red[2 * gidx + 1];
        float mean = S / (float)len;
        float var = S2 / (float)len - mean * mean;
        g_stats[2 * gidx]     = mean;
        g_stats[2 * gidx + 1] = rsqrtf(fmaxf(var, 0.f) + 1e-5f);
        g_red[2 * gidx] = 0.f;
        g_red[2 * gidx + 1] = 0.f;
    }
}

__global__ void reset_rowmax(int n)
{
    int i = blockIdx.x * 256 + threadIdx.x;
    if (i < n) g_rowmax_u[i] = 0u;
}

// ---------------------------------------------------------------------------
// Launch sequence
// ---------------------------------------------------------------------------
static inline int smem_bytes(int ASZ, int BSZ) { return (2 * (ASZ + BSZ)) * 4; }

extern "C" void kernel_launch(void* const* d_in, const int* in_sizes, int n_in,
                              void* d_out, int out_size)
{
    const float* Q[4]  = { (const float*)d_in[0], (const float*)d_in[1],
                           (const float*)d_in[2], (const float*)d_in[3] };
    const float* KV    = (const float*)d_in[4];
    const float* Wk    = (const float*)d_in[5];
    const float* Wv    = (const float*)d_in[6];
    const float* Wq[4] = { (const float*)d_in[7], (const float*)d_in[8],
                           (const float*)d_in[9], (const float*)d_in[10] };
    const float* Wo[4] = { (const float*)d_in[11], (const float*)d_in[12],
                           (const float*)d_in[13], (const float*)d_in[14] };
    float* out = (float*)d_out;

    float *Kt, *KVt, *Qt, *attn, *outpre;
    cudaGetSymbolAddress((void**)&Kt,     g_Kt);
    cudaGetSymbolAddress((void**)&KVt,    g_KVt);
    cudaGetSymbolAddress((void**)&Qt,     g_Qt);
    cudaGetSymbolAddress((void**)&attn,   g_attn);
    cudaGetSymbolAddress((void**)&outpre, g_outpre);

    const int SM_NN   = smem_bytes(128 * 36, 64 * 36);
    const int SM_TT   = smem_bytes(32 * 136, 32 * 72);
    const int SM_TT64 = smem_bytes(32 * 72, 32 * 72);
    const int SM_AV   = SM_NN + 128 * 4;

    cudaFuncSetAttribute(gemm_pipe<128, true,  false, false, false>,
                         cudaFuncAttributeMaxDynamicSharedMemorySize, SM_NN);
    cudaFuncSetAttribute(gemm_pipe<128, false, false, false, false>,
                         cudaFuncAttributeMaxDynamicSharedMemorySize, SM_NN);
    cudaFuncSetAttribute(gemm_pipe<128, false, true, true, true>,
                         cudaFuncAttributeMaxDynamicSharedMemorySize, SM_TT);
    cudaFuncSetAttribute(gemm_pipe<64, false, true, true, true>,
                         cudaFuncAttributeMaxDynamicSharedMemorySize, SM_TT64);
    cudaFuncSetAttribute(gemm_av,
                         cudaFuncAttributeMaxDynamicSharedMemorySize, SM_AV);

    const float inv_scale = 1.0f / sqrtf((float)SDIM);

    // KV transform: Kt = KV @ Wk^T ; KVt = Kt @ Wv^T (per-head weights)
    gemm_pipe<128, true, false, false, false><<<dim3(SDIM / 64, 1, GB), 256, SM_NN>>>(
        KV, Wk, Kt, NSEQ, SDIM, SDIM,
        (long)NSEQ * SDIM, (long)SDIM * SDIM, (long)NSEQ * SDIM, 1.f);
    gemm_pipe<128, true, false, false, false><<<dim3(SDIM / 64, 1, GB), 256, SM_NN>>>(
        Kt, Wv, KVt, NSEQ, SDIM, SDIM,
        (long)NSEQ * SDIM, (long)SDIM * SDIM, (long)NSEQ * SDIM, 1.f);

    const int Cs[4] = { 64, 128, 256, 512 };
    long ooff = 0;
    for (int i = 0; i < 4; i++) {
        const int C = Cs[i];

        // Qt = Qh @ Wq^T : [128, C] per slice
        gemm_pipe<128, true, false, false, false><<<dim3(C / 64, 1, GB), 256, SM_NN>>>(
            Q[i], Wq[i], Qt, NSEQ, C, C,
            (long)NSEQ * C, (long)C * C, (long)NSEQ * C, 1.f);

        // clear row maxima for this branch
        reset_rowmax<<<(GB * C + 255) / 256, 256>>>(GB * C);

        // attn[c,s] = inv_scale * sum_n Qt[n,c] * KVt[n,s]  (+ fused stats/rowmax)
        if (C == 64) {
            gemm_pipe<64, false, true, true, true><<<dim3(SDIM / 64, 1, GB), 256, SM_TT64>>>(
                Qt, KVt, attn, C, SDIM, NSEQ,
                (long)NSEQ * C, (long)NSEQ * SDIM, (long)C * SDIM, inv_scale);
        } else {
            gemm_pipe<128, false, true, true, true><<<dim3(SDIM / 64, C / 128, GB), 256, SM_TT>>>(
                Qt, KVt, attn, C, SDIM, NSEQ,
                (long)NSEQ * C, (long)NSEQ * SDIM, (long)C * SDIM, inv_scale);
        }

        // per-slice rstd
        stats_fin<<<1, GB>>>(C * SDIM);

        // outpre[n,c] = softmax-AV fused
        gemm_av<<<dim3(C / 64, 1, GB), 256, SM_AV>>>(
            KVt, attn, outpre, C,
            (long)NSEQ * SDIM, (long)C * SDIM, (long)NSEQ * C);

        // Y = outpre @ Wo^T : [8192, C]
        gemm_pipe<128, false, false, false, false><<<dim3(C / 64, 8192 / 128, 1), 256, SM_NN>>>(
            outpre, Wo[i], out + ooff, 8192, C, C, 0, 0, 0, 1.f);

        ooff += 8192L * C;
    }
}

// round 14
// speedup vs baseline: 2.9465x; 1.0441x over previous
#include <cuda_runtime.h>
#include <cstdint>
#include <math.h>

// Problem constants
#define GB 64        // B*H batched slices
#define NSEQ 128     // tokens per head
#define SDIM 960     // K/V feature dim
#define BK 32
#define BN 64

// Scratch (device globals; no allocation allowed)
__device__ float g_Kt[GB * NSEQ * SDIM];
__device__ float g_KVt[GB * NSEQ * SDIM];
__device__ float g_Qt[GB * NSEQ * 512];
__device__ float g_attn[GB * 512 * SDIM];
__device__ float g_outpre[8192 * 512];
__device__ float g_stats[GB * 2];            // mean, rstd per slice
__device__ float g_red[GB * 2];              // atomic sum / sumsq (self-zeroing)
__device__ unsigned g_rowmax_u[GB * 960];    // per-branch disjoint regions

__device__ __forceinline__ unsigned f2tf32(float x) {
    unsigned u;
    asm("cvt.rna.tf32.f32 %0, %1;" : "=r"(u) : "f"(x));
    return u;
}
__device__ __forceinline__ float rnd_tf32(float x) {
    return __uint_as_float(f2tf32(x));
}

__device__ __forceinline__ void cpa16(unsigned int dst, const float* src) {
    asm volatile("cp.async.cg.shared.global [%0], [%1], 16;\n" :: "r"(dst), "l"(src));
}

// ordered-uint encode/decode for float atomicMax
__device__ __forceinline__ unsigned fenc(float x) {
    unsigned u = __float_as_uint(x);
    return (u & 0x80000000u) ? ~u : (u | 0x80000000u);
}
__device__ __forceinline__ float fdec(unsigned u) {
    return (u & 0x80000000u) ? __uint_as_float(u & 0x7fffffffu)
                             : __uint_as_float(~u);
}

template<bool CV>
__device__ __forceinline__ unsigned frag(float v) {
    return CV ? f2tf32(v) : __float_as_uint(v);
}

// ---------------------------------------------------------------------------
// Pipelined TF32 GEMM. C[m,n] = alpha * sum_k a(m,k) * b(n,k)
// AT: A global KxM row-major; else MxK. BT: B global KxN row-major; else NxK.
// EPI: logits epilogue — per-slice sum/sumsq atomics + per-row raw max.
// CVA/CVB: operand needs tf32 rounding at fragment load (raw external input).
// RND: round outputs to tf32 before store (producer-side rounding).
// ---------------------------------------------------------------------------
template<int BM, bool MODB, bool AT, bool BT, bool EPI, bool CVA, bool CVB, bool RND>
__global__ __launch_bounds__(256)
void gemm_pipe(const float* __restrict__ Ab, const float* __restrict__ Bb,
               float* __restrict__ Cb, int M, int N, int K,
               long sA, long sB, long sC, float alpha,
               unsigned* __restrict__ rowmax)
{
    constexpr int SA = AT ? (BM + 8) : (BK + 4);
    constexpr int SB = BT ? (BN + 8) : (BK + 4);
    constexpr int ASZ = AT ? BK * SA : BM * SA;
    constexpr int BSZ = BT ? BK * SB : BN * SB;
    constexpr int NT = (BM == 128) ? 4 : 2;

    extern __shared__ float sm[];
    float* As = sm;
    float* Bs = sm + 2 * ASZ;
    const unsigned int sA_u32 = (unsigned int)__cvta_generic_to_shared(As);
    const unsigned int sB_u32 = (unsigned int)__cvta_generic_to_shared(Bs);

    const int b = blockIdx.z;
    const float* A = Ab + (long)b * sA;
    const float* B = Bb + (MODB ? (long)(b & 7) : (long)b) * sB;
    float* C = Cb + (long)b * sC;

    const int bm = blockIdx.y * BM;
    const int bn = blockIdx.x * BN;
    const int tid = threadIdx.x;
    const int warp = tid >> 5, lane = tid & 31;
    const int g = lane >> 2, tg = lane & 3;
    const int wm = (BM == 128) ? (warp & 3) * 32 : (warp & 1) * 32;
    const int wn = (BM == 128) ? (warp >> 2) * 32 : (warp >> 1) * 16;

    float acc[2][NT][4];
#pragma unroll
    for (int i = 0; i < 2; i++)
#pragma unroll
        for (int j = 0; j < NT; j++)
#pragma unroll
            for (int c = 0; c < 4; c++) acc[i][j][c] = 0.f;

    auto load_tiles = [&](int stage, int k0) {
        if (AT) {
            constexpr int CH = BM / 4;
#pragma unroll
            for (int t = 0; t < (BK * CH) / 256; t++) {
                int slot = tid + t * 256;
                int kk = slot / CH, m4 = slot % CH;
                cpa16(sA_u32 + (stage * ASZ + kk * SA + m4 * 4) * 4,
                      A + (long)(k0 + kk) * M + bm + m4 * 4);
            }
        } else {
            constexpr int CH = BK / 4;
#pragma unroll
            for (int t = 0; t < (BM * CH) / 256; t++) {
                int slot = tid + t * 256;
                int m = slot / CH, c4 = slot % CH;
                cpa16(sA_u32 + (stage * ASZ + m * SA + c4 * 4) * 4,
                      A + (long)(bm + m) * K + k0 + c4 * 4);
            }
        }
        if (BT) {
            constexpr int CH = BN / 4;
#pragma unroll
            for (int t = 0; t < (BK * CH) / 256; t++) {
                int slot = tid + t * 256;
                int kk = slot / CH, n4 = slot % CH;
                cpa16(sB_u32 + (stage * BSZ + kk * SB + n4 * 4) * 4,
                      B + (long)(k0 + kk) * N + bn + n4 * 4);
            }
        } else {
            constexpr int CH = BK / 4;
#pragma unroll
            for (int t = 0; t < (BN * CH) / 256; t++) {
                int slot = tid + t * 256;
                int n = slot / CH, c4 = slot & (CH - 1);
                cpa16(sB_u32 + (stage * BSZ + n * SB + c4 * 4) * 4,
                      B + (long)(bn + n) * K + k0 + c4 * 4);
            }
        }
        asm volatile("cp.async.commit_group;\n");
    };

    const int T = K / BK;
    load_tiles(0, 0);

    for (int t = 0; t < T; t++) {
        if (t + 1 < T) {
            load_tiles((t + 1) & 1, (t + 1) * BK);
            asm volatile("cp.async.wait_group 1;\n");
        } else {
            asm volatile("cp.async.wait_group 0;\n");
        }
        __syncthreads();

        const float* Ast = As + (t & 1) * ASZ;
        const float* Bst = Bs + (t & 1) * BSZ;
#pragma unroll
        for (int ks = 0; ks < BK; ks += 8) {
            unsigned a[2][4], bf[NT][2];
#pragma unroll
            for (int mt = 0; mt < 2; mt++) {
                int m = wm + mt * 16 + g;
                if (AT) {
                    a[mt][0] = frag<CVA>(Ast[(ks + tg) * SA + m]);
                    a[mt][1] = frag<CVA>(Ast[(ks + tg) * SA + m + 8]);
                    a[mt][2] = frag<CVA>(Ast[(ks + tg + 4) * SA + m]);
                    a[mt][3] = frag<CVA>(Ast[(ks + tg + 4) * SA + m + 8]);
                } else {
                    a[mt][0] = frag<CVA>(Ast[m * SA + ks + tg]);
                    a[mt][1] = frag<CVA>(Ast[(m + 8) * SA + ks + tg]);
                    a[mt][2] = frag<CVA>(Ast[m * SA + ks + tg + 4]);
                    a[mt][3] = frag<CVA>(Ast[(m + 8) * SA + ks + tg + 4]);
                }
            }
#pragma unroll
            for (int nt = 0; nt < NT; nt++) {
                int n = wn + nt * 8 + g;
                if (BT) {
                    bf[nt][0] = frag<CVB>(Bst[(ks + tg) * SB + n]);
                    bf[nt][1] = frag<CVB>(Bst[(ks + tg + 4) * SB + n]);
                } else {
                    bf[nt][0] = frag<CVB>(Bst[n * SB + ks + tg]);
                    bf[nt][1] = frag<CVB>(Bst[n * SB + ks + tg + 4]);
                }
            }
#pragma unroll
            for (int mt = 0; mt < 2; mt++)
#pragma unroll
                for (int nt = 0; nt < NT; nt++) {
                    asm volatile(
                        "mma.sync.aligned.m16n8k8.row.col.f32.tf32.tf32.f32 "
                        "{%0,%1,%2,%3}, {%4,%5,%6,%7}, {%8,%9}, {%0,%1,%2,%3};\n"
                        : "+f"(acc[mt][nt][0]), "+f"(acc[mt][nt][1]),
                          "+f"(acc[mt][nt][2]), "+f"(acc[mt][nt][3])
                        : "r"(a[mt][0]), "r"(a[mt][1]), "r"(a[mt][2]), "r"(a[mt][3]),
                          "r"(bf[nt][0]), "r"(bf[nt][1]));
                }
        }
        __syncthreads();
    }

    float psum = 0.f, psq = 0.f;
#pragma unroll
    for (int mt = 0; mt < 2; mt++) {
        int row = bm + wm + mt * 16 + g;
        float r0m = -3.0e38f, r1m = -3.0e38f;
#pragma unroll
        for (int nt = 0; nt < NT; nt++) {
            int col = bn + wn + nt * 8 + tg * 2;
            float2 v0 = make_float2(acc[mt][nt][0] * alpha, acc[mt][nt][1] * alpha);
            float2 v1 = make_float2(acc[mt][nt][2] * alpha, acc[mt][nt][3] * alpha);
            if (RND) {
                v0.x = rnd_tf32(v0.x); v0.y = rnd_tf32(v0.y);
                v1.x = rnd_tf32(v1.x); v1.y = rnd_tf32(v1.y);
            }
            *(float2*)(C + (long)row * N + col)       = v0;
            *(float2*)(C + (long)(row + 8) * N + col) = v1;
            if (EPI) {
                psum += v0.x + v0.y + v1.x + v1.y;
                psq = fmaf(v0.x, v0.x, fmaf(v0.y, v0.y,
                      fmaf(v1.x, v1.x, fmaf(v1.y, v1.y, psq))));
                r0m = fmaxf(r0m, fmaxf(v0.x, v0.y));
                r1m = fmaxf(r1m, fmaxf(v1.x, v1.y));
            }
        }
        if (EPI) {
            atomicMax(&rowmax[(long)b * M + row],     fenc(r0m));
            atomicMax(&rowmax[(long)b * M + row + 8], fenc(r1m));
        }
    }

    if (EPI) {
        __shared__ float red_sh[16];
#pragma unroll
        for (int o = 16; o > 0; o >>= 1) {
            psum += __shfl_down_sync(0xffffffffu, psum, o);
            psq  += __shfl_down_sync(0xffffffffu, psq,  o);
        }
        if (lane == 0) { red_sh[warp] = psum; red_sh[warp + 8] = psq; }
        __syncthreads();
        if (tid == 0) {
            float S = 0.f, S2 = 0.f;
            for (int i = 0; i < 8; i++) { S += red_sh[i]; S2 += red_sh[i + 8]; }
            atomicAdd(&g_red[2 * b],     S);
            atomicAdd(&g_red[2 * b + 1], S2);
        }
    }
}

// ---------------------------------------------------------------------------
// AV GEMM with fused softmax. outpre[m, n] = sum_k A[m,k] * p(n,k) / Z_n
// A = KVt (tf32-rounded, MxK row-major), Braw = attn (NxK row-major).
// p = rna_tf32(exp((x - rawmax_row) * rstd)); Z from rounded p.
// Inner loop is cvt-free. Output rounded to tf32 (feeds Wo GEMM).
// ---------------------------------------------------------------------------
__global__ __launch_bounds__(256)
void gemm_av(const float* __restrict__ Ab, const float* __restrict__ Bb,
             float* __restrict__ Cb, int N, long sA, long sB, long sC,
             const unsigned* __restrict__ rowmax)
{
    constexpr int BM = 128;
    constexpr int SA = BK + 4;
    constexpr int SB = BK + 4;
    constexpr int ASZ = BM * SA;
    constexpr int BSZ = BN * SB;
    constexpr int K = SDIM;

    extern __shared__ float sm[];
    float* As = sm;
    float* Bs = sm + 2 * ASZ;
    float* Zsh = sm + 2 * ASZ + 2 * BSZ;     // [64]
    float* Rmx = Zsh + 64;                   // [64]
    const unsigned int sA_u32 = (unsigned int)__cvta_generic_to_shared(As);
    const unsigned int sB_u32 = (unsigned int)__cvta_generic_to_shared(Bs);

    const int b = blockIdx.z;
    const float* A = Ab + (long)b * sA;
    const float* B = Bb + (long)b * sB;
    float* C = Cb + (long)b * sC;

    const int bn = blockIdx.x * BN;
    const int tid = threadIdx.x;
    const int warp = tid >> 5, lane = tid & 31;
    const int g = lane >> 2, tg = lane & 3;
    const int wm = (warp & 3) * 32;
    const int wn = (warp >> 2) * 32;
    const float rstd = g_stats[2 * b + 1];

    if (tid < 64) {
        Zsh[tid] = 0.f;
        Rmx[tid] = fdec(rowmax[(long)b * N + bn + tid]);
    }

    float acc[2][4][4];
#pragma unroll
    for (int i = 0; i < 2; i++)
#pragma unroll
        for (int j = 0; j < 4; j++)
#pragma unroll
            for (int c = 0; c < 4; c++) acc[i][j][c] = 0.f;

    auto load_tiles = [&](int stage, int k0) {
#pragma unroll
        for (int t = 0; t < 4; t++) {               // A: 128 rows x 8 f4
            int slot = tid + t * 256;
            int m = slot >> 3, c4 = slot & 7;
            cpa16(sA_u32 + (stage * ASZ + m * SA + c4 * 4) * 4,
                  A + (long)m * K + k0 + c4 * 4);
        }
#pragma unroll
        for (int t = 0; t < 2; t++) {               // B: 64 rows x 8 f4
            int slot = tid + t * 256;
            int n = slot >> 3, c4 = slot & 7;
            cpa16(sB_u32 + (stage * BSZ + n * SB + c4 * 4) * 4,
                  B + (long)(bn + n) * K + k0 + c4 * 4);
        }
        asm volatile("cp.async.commit_group;\n");
    };

    const int T = K / BK;
    load_tiles(0, 0);

    for (int t = 0; t < T; t++) {
        if (t + 1 < T) {
            load_tiles((t + 1) & 1, (t + 1) * BK);
            asm volatile("cp.async.wait_group 1;\n");
        } else {
            asm volatile("cp.async.wait_group 0;\n");
        }
        __syncthreads();

        float* Bst = Bs + (t & 1) * BSZ;
        // transform: p = rna(exp((x - rawmax) * rstd)), accumulate Z
        {
            int n = tid >> 2;
            int k0 = (tid & 3) * 8;
            float rm = Rmx[n];
            float* p = Bst + n * SB + k0;
            float4 v0 = *(float4*)p;
            float4 v1 = *(float4*)(p + 4);
            v0.x = rnd_tf32(__expf((v0.x - rm) * rstd));
            v0.y = rnd_tf32(__expf((v0.y - rm) * rstd));
            v0.z = rnd_tf32(__expf((v0.z - rm) * rstd));
            v0.w = rnd_tf32(__expf((v0.w - rm) * rstd));
            v1.x = rnd_tf32(__expf((v1.x - rm) * rstd));
            v1.y = rnd_tf32(__expf((v1.y - rm) * rstd));
            v1.z = rnd_tf32(__expf((v1.z - rm) * rstd));
            v1.w = rnd_tf32(__expf((v1.w - rm) * rstd));
            *(float4*)p = v0;
            *(float4*)(p + 4) = v1;
            float part = v0.x + v0.y + v0.z + v0.w + v1.x + v1.y + v1.z + v1.w;
            part += __shfl_down_sync(0xffffffffu, part, 2);
            part += __shfl_down_sync(0xffffffffu, part, 1);
            if ((lane & 3) == 0) atomicAdd(&Zsh[n], part);
        }
        __syncthreads();

        const float* Ast = As + (t & 1) * ASZ;
#pragma unroll
        for (int ks = 0; ks < BK; ks += 8) {
            unsigned a[2][4], bf[4][2];
#pragma unroll
            for (int mt = 0; mt < 2; mt++) {
                int m = wm + mt * 16 + g;
                a[mt][0] = __float_as_uint(Ast[m * SA + ks + tg]);
                a[mt][1] = __float_as_uint(Ast[(m + 8) * SA + ks + tg]);
                a[mt][2] = __float_as_uint(Ast[m * SA + ks + tg + 4]);
                a[mt][3] = __float_as_uint(Ast[(m + 8) * SA + ks + tg + 4]);
            }
#pragma unroll
            for (int nt = 0; nt < 4; nt++) {
                int n = wn + nt * 8 + g;
                bf[nt][0] = __float_as_uint(Bst[n * SB + ks + tg]);
                bf[nt][1] = __float_as_uint(Bst[n * SB + ks + tg + 4]);
            }
#pragma unroll
            for (int mt = 0; mt < 2; mt++)
#pragma unroll
                for (int nt = 0; nt < 4; nt++) {
                    asm volatile(
                        "mma.sync.aligned.m16n8k8.row.col.f32.tf32.tf32.f32 "
                        "{%0,%1,%2,%3}, {%4,%5,%6,%7}, {%8,%9}, {%0,%1,%2,%3};\n"
                        : "+f"(acc[mt][nt][0]), "+f"(acc[mt][nt][1]),
                          "+f"(acc[mt][nt][2]), "+f"(acc[mt][nt][3])
                        : "r"(a[mt][0]), "r"(a[mt][1]), "r"(a[mt][2]), "r"(a[mt][3]),
                          "r"(bf[nt][0]), "r"(bf[nt][1]));
                }
        }
        __syncthreads();
    }

#pragma unroll
    for (int mt = 0; mt < 2; mt++) {
        int row = wm + mt * 16 + g;
#pragma unroll
        for (int nt = 0; nt < 4; nt++) {
            int cl = wn + nt * 8 + tg * 2;
            float iz0 = 1.f / Zsh[cl], iz1 = 1.f / Zsh[cl + 1];
            int col = bn + cl;
            float2 v0 = make_float2(rnd_tf32(acc[mt][nt][0] * iz0),
                                    rnd_tf32(acc[mt][nt][1] * iz1));
            float2 v1 = make_float2(rnd_tf32(acc[mt][nt][2] * iz0),
                                    rnd_tf32(acc[mt][nt][3] * iz1));
            *(float2*)(C + (long)row * N + col)       = v0;
            *(float2*)(C + (long)(row + 8) * N + col) = v1;
        }
    }
}

// ---------------------------------------------------------------------------
// finalize + resets
// ---------------------------------------------------------------------------
__global__ void stats_fin(int len)
{
    int gidx = threadIdx.x;
    if (gidx < GB) {
        float S = g_red[2 * gidx], S2 = g_red[2 * gidx + 1];
        float mean = S / (float)len;
        float var = S2 / (float)len - mean * mean;
        g_stats[2 * gidx]     = mean;
        g_stats[2 * gidx + 1] = rsqrtf(fmaxf(var, 0.f) + 1e-5f);
        g_red[2 * gidx] = 0.f;
        g_red[2 * gidx + 1] = 0.f;
    }
}

__global__ void reset_rowmax(int n)
{
    int i = blockIdx.x * 256 + threadIdx.x;
    if (i < n) g_rowmax_u[i] = 0u;
}

// ---------------------------------------------------------------------------
// Launch sequence
// ---------------------------------------------------------------------------
static inline int smem_bytes(int ASZ, int BSZ) { return (2 * (ASZ + BSZ)) * 4; }

extern "C" void kernel_launch(void* const* d_in, const int* in_sizes, int n_in,
                              void* d_out, int out_size)
{
    const float* Q[4]  = { (const float*)d_in[0], (const float*)d_in[1],
                           (const float*)d_in[2], (const float*)d_in[3] };
    const float* KV    = (const float*)d_in[4];
    const float* Wk    = (const float*)d_in[5];
    const float* Wv    = (const float*)d_in[6];
    const float* Wq[4] = { (const float*)d_in[7], (const float*)d_in[8],
                           (const float*)d_in[9], (const float*)d_in[10] };
    const float* Wo[4] = { (const float*)d_in[11], (const float*)d_in[12],
                           (const float*)d_in[13], (const float*)d_in[14] };
    float* out = (float*)d_out;

    float *Kt, *KVt, *Qt, *attn, *outpre;
    unsigned* rowmax;
    cudaGetSymbolAddress((void**)&Kt,     g_Kt);
    cudaGetSymbolAddress((void**)&KVt,    g_KVt);
    cudaGetSymbolAddress((void**)&Qt,     g_Qt);
    cudaGetSymbolAddress((void**)&attn,   g_attn);
    cudaGetSymbolAddress((void**)&outpre, g_outpre);
    cudaGetSymbolAddress((void**)&rowmax, g_rowmax_u);

    const int SM_NN   = smem_bytes(128 * 36, 64 * 36);
    const int SM_TT   = smem_bytes(32 * 136, 32 * 72);
    const int SM_TT64 = smem_bytes(32 * 72, 32 * 72);
    const int SM_AV   = SM_NN + 128 * 4;

    // instantiations: <BM, MODB, AT, BT, EPI, CVA, CVB, RND>
    auto* kIn   = gemm_pipe<128, true,  false, false, false, true,  true,  true>;  // KVt1, Qt
    auto* kKt2  = gemm_pipe<128, true,  false, false, false, false, true,  true>;  // KVt2
    auto* kLg128= gemm_pipe<128, false, true,  true,  true,  false, false, false>; // logits BM128
    auto* kLg64 = gemm_pipe<64,  false, true,  true,  true,  false, false, false>; // logits BM64
    auto* kWo   = gemm_pipe<128, false, false, false, false, false, true,  false>; // out proj

    cudaFuncSetAttribute(kIn,    cudaFuncAttributeMaxDynamicSharedMemorySize, SM_NN);
    cudaFuncSetAttribute(kKt2,   cudaFuncAttributeMaxDynamicSharedMemorySize, SM_NN);
    cudaFuncSetAttribute(kLg128, cudaFuncAttributeMaxDynamicSharedMemorySize, SM_TT);
    cudaFuncSetAttribute(kLg64,  cudaFuncAttributeMaxDynamicSharedMemorySize, SM_TT64);
    cudaFuncSetAttribute(kWo,    cudaFuncAttributeMaxDynamicSharedMemorySize, SM_NN);
    cudaFuncSetAttribute(gemm_av, cudaFuncAttributeMaxDynamicSharedMemorySize, SM_AV);

    const float inv_scale = 1.0f / sqrtf((float)SDIM);

    // clear all per-branch rowmax regions once (replayed at sequence start)
    reset_rowmax<<<(GB * 960 + 255) / 256, 256>>>(GB * 960);

    // KV transform: Kt = KV @ Wk^T ; KVt = Kt @ Wv^T (per-head weights)
    kIn<<<dim3(SDIM / 64, 1, GB), 256, SM_NN>>>(
        KV, Wk, Kt, NSEQ, SDIM, SDIM,
        (long)NSEQ * SDIM, (long)SDIM * SDIM, (long)NSEQ * SDIM, 1.f, nullptr);
    kKt2<<<dim3(SDIM / 64, 1, GB), 256, SM_NN>>>(
        Kt, Wv, KVt, NSEQ, SDIM, SDIM,
        (long)NSEQ * SDIM, (long)SDIM * SDIM, (long)NSEQ * SDIM, 1.f, nullptr);

    const int Cs[4]    = { 64, 128, 256, 512 };
    const int Coff[4]  = { 0, 64, 192, 448 };     // rowmax region offsets (per slice)
    long ooff = 0;
    for (int i = 0; i < 4; i++) {
        const int C = Cs[i];
        unsigned* rmx = rowmax + (long)GB * Coff[i];

        // Qt = Qh @ Wq^T : [128, C] per slice
        kIn<<<dim3(C / 64, 1, GB), 256, SM_NN>>>(
            Q[i], Wq[i], Qt, NSEQ, C, C,
            (long)NSEQ * C, (long)C * C, (long)NSEQ * C, 1.f, nullptr);

        // attn[c,s] = inv_scale * sum_n Qt[n,c] * KVt[n,s]  (+ fused stats/rowmax)
        if (C == 64) {
            kLg64<<<dim3(SDIM / 64, 1, GB), 256, SM_TT64>>>(
                Qt, KVt, attn, C, SDIM, NSEQ,
                (long)NSEQ * C, (long)NSEQ * SDIM, (long)C * SDIM, inv_scale, rmx);
        } else {
            kLg128<<<dim3(SDIM / 64, C / 128, GB), 256, SM_TT>>>(
                Qt, KVt, attn, C, SDIM, NSEQ,
                (long)NSEQ * C, (long)NSEQ * SDIM, (long)C * SDIM, inv_scale, rmx);
        }

        // per-slice rstd
        stats_fin<<<1, GB>>>(C * SDIM);

        // outpre[n,c] = softmax-AV fused
        gemm_av<<<dim3(C / 64, 1, GB), 256, SM_AV>>>(
            KVt, attn, outpre, C,
            (long)NSEQ * SDIM, (long)C * SDIM, (long)NSEQ * C, rmx);

        // Y = outpre @ Wo^T : [8192, C]
        kWo<<<dim3(C / 64, 8192 / 128, 1), 256, SM_NN>>>(
            outpre, Wo[i], out + ooff, 8192, C, C, 0, 0, 0, 1.f, nullptr);

        ooff += 8192L * C;
    }
}

// round 16
// speedup vs baseline: 3.2849x; 1.1148x over previous
#include <cuda_runtime.h>
#include <cstdint>
#include <math.h>

// Problem constants
#define GB 64        // B*H batched slices
#define NSEQ 128     // tokens per head
#define SDIM 960     // K/V feature dim
#define BK 32
#define BN 64
#define CSUM 960     // 64+128+256+512
#define INV_SCALE 0.032274861f   // fp32(1/sqrt(960))

// Scratch (device globals; no allocation allowed)
__device__ float g_Kt[GB * NSEQ * SDIM];
__device__ float g_KVt[GB * NSEQ * SDIM];
__device__ float g_Qt[GB * NSEQ * CSUM];            // per-branch regions
__device__ float g_attn[(long)GB * CSUM * SDIM];    // per-branch regions (236 MB)
__device__ float g_outpre[8192 * CSUM];             // per-branch regions
__device__ float g_stats[4 * GB * 2];               // [br][slice][mean,rstd]
__device__ float g_red[4 * GB * 2];                 // self-zeroing atomics
__device__ unsigned g_rowmax_u[GB * CSUM];          // per-branch regions

__device__ __forceinline__ unsigned f2tf32(float x) {
    unsigned u;
    asm("cvt.rna.tf32.f32 %0, %1;" : "=r"(u) : "f"(x));
    return u;
}
__device__ __forceinline__ float rnd_tf32(float x) {
    return __uint_as_float(f2tf32(x));
}
__device__ __forceinline__ void cpa16(unsigned int dst, const float* src) {
    asm volatile("cp.async.cg.shared.global [%0], [%1], 16;\n" :: "r"(dst), "l"(src));
}
__device__ __forceinline__ unsigned fenc(float x) {
    unsigned u = __float_as_uint(x);
    return (u & 0x80000000u) ? ~u : (u | 0x80000000u);
}
__device__ __forceinline__ float fdec(unsigned u) {
    return (u & 0x80000000u) ? __uint_as_float(u & 0x7fffffffu)
                             : __uint_as_float(~u);
}
template<bool CV>
__device__ __forceinline__ unsigned frag(float v) {
    return CV ? f2tf32(v) : __float_as_uint(v);
}

// branch tables: C = 64<<br, x-tile bases {0,1,3,7}, Coff {0,64,192,448}
__device__ __forceinline__ void br_from_x(int t, int& br, int& lt) {
    br = (t >= 7) ? 3 : (t >= 3) ? 2 : (t >= 1) ? 1 : 0;
    const int base = (br == 0) ? 0 : (br == 1) ? 1 : (br == 2) ? 3 : 7;
    lt = t - base;
}
__device__ __forceinline__ int coff_of(int br) {
    return (br == 0) ? 0 : (br == 1) ? 64 : (br == 2) ? 192 : 448;
}

// ---------------------------------------------------------------------------
// GEMM core. C[m,n] = alpha * sum_k a(m,k) * b(n,k).  Pointers pre-offset.
// ---------------------------------------------------------------------------
template<int BM, bool AT, bool BT, bool EPI, bool CVA, bool CVB, bool RND>
__device__ __forceinline__ void gemm_core(
    const float* __restrict__ A, const float* __restrict__ B, float* __restrict__ C,
    int M, int N, int K, int bm, int bn, int b, float alpha,
    unsigned* __restrict__ rowmax, float* __restrict__ red)
{
    constexpr int SA = AT ? (BM + 8) : (BK + 4);
    constexpr int SB = BT ? (BN + 8) : (BK + 4);
    constexpr int ASZ = AT ? BK * SA : BM * SA;
    constexpr int BSZ = BT ? BK * SB : BN * SB;
    constexpr int NT = (BM == 128) ? 4 : 2;

    extern __shared__ float sm[];
    float* As = sm;
    float* Bs = sm + 2 * ASZ;
    const unsigned int sA_u32 = (unsigned int)__cvta_generic_to_shared(As);
    const unsigned int sB_u32 = (unsigned int)__cvta_generic_to_shared(Bs);

    const int tid = threadIdx.x;
    const int warp = tid >> 5, lane = tid & 31;
    const int g = lane >> 2, tg = lane & 3;
    const int wm = (BM == 128) ? (warp & 3) * 32 : (warp & 1) * 32;
    const int wn = (BM == 128) ? (warp >> 2) * 32 : (warp >> 1) * 16;

    float acc[2][NT][4];
#pragma unroll
    for (int i = 0; i < 2; i++)
#pragma unroll
        for (int j = 0; j < NT; j++)
#pragma unroll
            for (int c = 0; c < 4; c++) acc[i][j][c] = 0.f;

    auto load_tiles = [&](int stage, int k0) {
        if (AT) {
            constexpr int CH = BM / 4;
#pragma unroll
            for (int t = 0; t < (BK * CH) / 256; t++) {
                int slot = tid + t * 256;
                int kk = slot / CH, m4 = slot % CH;
                cpa16(sA_u32 + (stage * ASZ + kk * SA + m4 * 4) * 4,
                      A + (long)(k0 + kk) * M + bm + m4 * 4);
            }
        } else {
            constexpr int CH = BK / 4;
#pragma unroll
            for (int t = 0; t < (BM * CH) / 256; t++) {
                int slot = tid + t * 256;
                int m = slot / CH, c4 = slot % CH;
                cpa16(sA_u32 + (stage * ASZ + m * SA + c4 * 4) * 4,
                      A + (long)(bm + m) * K + k0 + c4 * 4);
            }
        }
        if (BT) {
            constexpr int CH = BN / 4;
#pragma unroll
            for (int t = 0; t < (BK * CH) / 256; t++) {
                int slot = tid + t * 256;
                int kk = slot / CH, n4 = slot % CH;
                cpa16(sB_u32 + (stage * BSZ + kk * SB + n4 * 4) * 4,
                      B + (long)(k0 + kk) * N + bn + n4 * 4);
            }
        } else {
            constexpr int CH = BK / 4;
#pragma unroll
            for (int t = 0; t < (BN * CH) / 256; t++) {
                int slot = tid + t * 256;
                int n = slot / CH, c4 = slot % CH;
                cpa16(sB_u32 + (stage * BSZ + n * SB + c4 * 4) * 4,
                      B + (long)(bn + n) * K + k0 + c4 * 4);
            }
        }
        asm volatile("cp.async.commit_group;\n");
    };

    const int T = K / BK;
    load_tiles(0, 0);

    for (int t = 0; t < T; t++) {
        if (t + 1 < T) {
            load_tiles((t + 1) & 1, (t + 1) * BK);
            asm volatile("cp.async.wait_group 1;\n");
        } else {
            asm volatile("cp.async.wait_group 0;\n");
        }
        __syncthreads();

        const float* Ast = As + (t & 1) * ASZ;
        const float* Bst = Bs + (t & 1) * BSZ;
#pragma unroll
        for (int ks = 0; ks < BK; ks += 8) {
            unsigned a[2][4], bf[NT][2];
#pragma unroll
            for (int mt = 0; mt < 2; mt++) {
                int m = wm + mt * 16 + g;
                if (AT) {
                    a[mt][0] = frag<CVA>(Ast[(ks + tg) * SA + m]);
                    a[mt][1] = frag<CVA>(Ast[(ks + tg) * SA + m + 8]);
                    a[mt][2] = frag<CVA>(Ast[(ks + tg + 4) * SA + m]);
                    a[mt][3] = frag<CVA>(Ast[(ks + tg + 4) * SA + m + 8]);
                } else {
                    a[mt][0] = frag<CVA>(Ast[m * SA + ks + tg]);
                    a[mt][1] = frag<CVA>(Ast[(m + 8) * SA + ks + tg]);
                    a[mt][2] = frag<CVA>(Ast[m * SA + ks + tg + 4]);
                    a[mt][3] = frag<CVA>(Ast[(m + 8) * SA + ks + tg + 4]);
                }
            }
#pragma unroll
            for (int nt = 0; nt < NT; nt++) {
                int n = wn + nt * 8 + g;
                if (BT) {
                    bf[nt][0] = frag<CVB>(Bst[(ks + tg) * SB + n]);
                    bf[nt][1] = frag<CVB>(Bst[(ks + tg + 4) * SB + n]);
                } else {
                    bf[nt][0] = frag<CVB>(Bst[n * SB + ks + tg]);
                    bf[nt][1] = frag<CVB>(Bst[n * SB + ks + tg + 4]);
                }
            }
#pragma unroll
            for (int mt = 0; mt < 2; mt++)
#pragma unroll
                for (int nt = 0; nt < NT; nt++) {
                    asm volatile(
                        "mma.sync.aligned.m16n8k8.row.col.f32.tf32.tf32.f32 "
                        "{%0,%1,%2,%3}, {%4,%5,%6,%7}, {%8,%9}, {%0,%1,%2,%3};\n"
                        : "+f"(acc[mt][nt][0]), "+f"(acc[mt][nt][1]),
                          "+f"(acc[mt][nt][2]), "+f"(acc[mt][nt][3])
                        : "r"(a[mt][0]), "r"(a[mt][1]), "r"(a[mt][2]), "r"(a[mt][3]),
                          "r"(bf[nt][0]), "r"(bf[nt][1]));
                }
        }
        __syncthreads();
    }

    float psum = 0.f, psq = 0.f;
#pragma unroll
    for (int mt = 0; mt < 2; mt++) {
        int row = bm + wm + mt * 16 + g;
        float r0m = -3.0e38f, r1m = -3.0e38f;
#pragma unroll
        for (int nt = 0; nt < NT; nt++) {
            int col = bn + wn + nt * 8 + tg * 2;
            float2 v0 = make_float2(acc[mt][nt][0] * alpha, acc[mt][nt][1] * alpha);
            float2 v1 = make_float2(acc[mt][nt][2] * alpha, acc[mt][nt][3] * alpha);
            if (RND) {
                v0.x = rnd_tf32(v0.x); v0.y = rnd_tf32(v0.y);
                v1.x = rnd_tf32(v1.x); v1.y = rnd_tf32(v1.y);
            }
            *(float2*)(C + (long)row * N + col)       = v0;
            *(float2*)(C + (long)(row + 8) * N + col) = v1;
            if (EPI) {
                psum += v0.x + v0.y + v1.x + v1.y;
                psq = fmaf(v0.x, v0.x, fmaf(v0.y, v0.y,
                      fmaf(v1.x, v1.x, fmaf(v1.y, v1.y, psq))));
                r0m = fmaxf(r0m, fmaxf(v0.x, v0.y));
                r1m = fmaxf(r1m, fmaxf(v1.x, v1.y));
            }
        }
        if (EPI) {
            atomicMax(&rowmax[(long)b * M + row],     fenc(r0m));
            atomicMax(&rowmax[(long)b * M + row + 8], fenc(r1m));
        }
    }

    if (EPI) {
        __shared__ float red_sh[16];
#pragma unroll
        for (int o = 16; o > 0; o >>= 1) {
            psum += __shfl_down_sync(0xffffffffu, psum, o);
            psq  += __shfl_down_sync(0xffffffffu, psq,  o);
        }
        if (lane == 0) { red_sh[warp] = psum; red_sh[warp + 8] = psq; }
        __syncthreads();
        if (tid == 0) {
            float S = 0.f, S2 = 0.f;
            for (int i = 0; i < 8; i++) { S += red_sh[i]; S2 += red_sh[i + 8]; }
            atomicAdd(&red[2 * b],     S);
            atomicAdd(&red[2 * b + 1], S2);
        }
    }
}

// ---------------------------------------------------------------------------
// Wrapper kernels
// ---------------------------------------------------------------------------
struct PtrsQt { const float* Q[4]; const float* Wq[4]; };
struct PtrsWo { const float* Wo[4]; float* out; };

__global__ __launch_bounds__(256)
void k_kv1(const float* __restrict__ KV, const float* __restrict__ Wk)
{
    int b = blockIdx.z;
    gemm_core<128, false, false, false, true, true, true>(
        KV + (long)b * NSEQ * SDIM, Wk + (long)(b & 7) * SDIM * SDIM,
        g_Kt + (long)b * NSEQ * SDIM,
        NSEQ, SDIM, SDIM, 0, blockIdx.x * 64, b, 1.f, nullptr, nullptr);
}

__global__ __launch_bounds__(256)
void k_kv2(const float* __restrict__ Wv)
{
    int b = blockIdx.z;
    gemm_core<128, false, false, false, false, true, true>(
        g_Kt + (long)b * NSEQ * SDIM, Wv + (long)(b & 7) * SDIM * SDIM,
        g_KVt + (long)b * NSEQ * SDIM,
        NSEQ, SDIM, SDIM, 0, blockIdx.x * 64, b, 1.f, nullptr, nullptr);
}

__global__ __launch_bounds__(256)
void k_qt_all(PtrsQt p)
{
    int br, lt;
    br_from_x(blockIdx.x, br, lt);
    const int C = 64 << br;
    const int Coff = coff_of(br);
    int b = blockIdx.z;
    gemm_core<128, false, false, false, true, true, true>(
        p.Q[br] + (long)b * NSEQ * C,
        p.Wq[br] + (long)(b & 7) * C * C,
        g_Qt + (long)GB * NSEQ * Coff + (long)b * NSEQ * C,
        NSEQ, C, C, 0, lt * 64, b, 1.f, nullptr, nullptr);
}

__global__ __launch_bounds__(256)
void k_lg64()
{
    int b = blockIdx.z;
    gemm_core<64, true, true, true, false, false, false>(
        g_Qt + (long)b * NSEQ * 64,
        g_KVt + (long)b * NSEQ * SDIM,
        g_attn + (long)b * 64 * SDIM,
        64, SDIM, NSEQ, 0, blockIdx.x * 64, b, INV_SCALE,
        g_rowmax_u, g_red);
}

__global__ __launch_bounds__(256)
void k_lg_rest()
{
    int yt = blockIdx.y;
    int br = (yt >= 3) ? 3 : (yt >= 1) ? 2 : 1;
    int ly = yt - ((br == 1) ? 0 : (br == 2) ? 1 : 3);
    const int C = 64 << br;
    const int Coff = coff_of(br);
    int b = blockIdx.z;
    gemm_core<128, true, true, true, false, false, false>(
        g_Qt + (long)GB * NSEQ * Coff + (long)b * NSEQ * C,
        g_KVt + (long)b * NSEQ * SDIM,
        g_attn + (long)GB * Coff * SDIM + (long)b * C * SDIM,
        C, SDIM, NSEQ, ly * 128, blockIdx.x * 64, b, INV_SCALE,
        g_rowmax_u + (long)GB * Coff, g_red + br * GB * 2);
}

__global__ void k_stats_all()
{
    int idx = threadIdx.x;
    if (idx < 4 * GB) {
        int br = idx >> 6;
        int len = (64 << br) * SDIM;
        float S = g_red[2 * idx], S2 = g_red[2 * idx + 1];
        float mean = S / (float)len;
        float var = S2 / (float)len - mean * mean;
        g_stats[2 * idx]     = mean;
        g_stats[2 * idx + 1] = rsqrtf(fmaxf(var, 0.f) + 1e-5f);
        g_red[2 * idx] = 0.f;
        g_red[2 * idx + 1] = 0.f;
    }
}

__global__ void k_reset_rowmax(int n)
{
    int i = blockIdx.x * 256 + threadIdx.x;
    if (i < n) g_rowmax_u[i] = 0u;
}

// AV with fused softmax, merged across branches.
__global__ __launch_bounds__(256)
void k_av_all()
{
    constexpr int BM = 128;
    constexpr int SA = BK + 4;
    constexpr int SB = BK + 4;
    constexpr int ASZ = BM * SA;
    constexpr int BSZ = BN * SB;
    constexpr int K = SDIM;

    int br, lt;
    br_from_x(blockIdx.x, br, lt);
    const int C = 64 << br;
    const int Coff = coff_of(br);
    const int b = blockIdx.z;
    const int bn = lt * 64;

    extern __shared__ float sm[];
    float* As = sm;
    float* Bs = sm + 2 * ASZ;
    float* Zsh = sm + 2 * ASZ + 2 * BSZ;     // [64]
    float* Rmx = Zsh + 64;                   // [64]
    const unsigned int sA_u32 = (unsigned int)__cvta_generic_to_shared(As);
    const unsigned int sB_u32 = (unsigned int)__cvta_generic_to_shared(Bs);

    const float* A = g_KVt + (long)b * NSEQ * SDIM;
    const float* B = g_attn + (long)GB * Coff * SDIM + (long)b * C * SDIM;
    float* Cp = g_outpre + (long)8192 * Coff + (long)b * NSEQ * C;
    const unsigned* rmx = g_rowmax_u + (long)GB * Coff + (long)b * C;
    const float rstd = g_stats[(br * GB + b) * 2 + 1];

    const int tid = threadIdx.x;
    const int warp = tid >> 5, lane = tid & 31;
    const int g = lane >> 2, tg = lane & 3;
    const int wm = (warp & 3) * 32;
    const int wn = (warp >> 2) * 32;

    if (tid < 64) {
        Zsh[tid] = 0.f;
        Rmx[tid] = fdec(rmx[bn + tid]);
    }

    float acc[2][4][4];
#pragma unroll
    for (int i = 0; i < 2; i++)
#pragma unroll
        for (int j = 0; j < 4; j++)
#pragma unroll
            for (int c = 0; c < 4; c++) acc[i][j][c] = 0.f;

    auto load_tiles = [&](int stage, int k0) {
#pragma unroll
        for (int t = 0; t < 4; t++) {
            int slot = tid + t * 256;
            int m = slot >> 3, c4 = slot & 7;
            cpa16(sA_u32 + (stage * ASZ + m * SA + c4 * 4) * 4,
                  A + (long)m * K + k0 + c4 * 4);
        }
#pragma unroll
        for (int t = 0; t < 2; t++) {
            int slot = tid + t * 256;
            int n = slot >> 3, c4 = slot & 7;
            cpa16(sB_u32 + (stage * BSZ + n * SB + c4 * 4) * 4,
                  B + (long)(bn + n) * K + k0 + c4 * 4);
        }
        asm volatile("cp.async.commit_group;\n");
    };

    const int T = K / BK;
    load_tiles(0, 0);

    for (int t = 0; t < T; t++) {
        if (t + 1 < T) {
            load_tiles((t + 1) & 1, (t + 1) * BK);
            asm volatile("cp.async.wait_group 1;\n");
        } else {
            asm volatile("cp.async.wait_group 0;\n");
        }
        __syncthreads();

        float* Bst = Bs + (t & 1) * BSZ;
        {
            int n = tid >> 2;
            int k0 = (tid & 3) * 8;
            float rm = Rmx[n];
            float* p = Bst + n * SB + k0;
            float4 v0 = *(float4*)p;
            float4 v1 = *(float4*)(p + 4);
            v0.x = rnd_tf32(__expf((v0.x - rm) * rstd));
            v0.y = rnd_tf32(__expf((v0.y - rm) * rstd));
            v0.z = rnd_tf32(__expf((v0.z - rm) * rstd));
            v0.w = rnd_tf32(__expf((v0.w - rm) * rstd));
            v1.x = rnd_tf32(__expf((v1.x - rm) * rstd));
            v1.y = rnd_tf32(__expf((v1.y - rm) * rstd));
            v1.z = rnd_tf32(__expf((v1.z - rm) * rstd));
            v1.w = rnd_tf32(__expf((v1.w - rm) * rstd));
            *(float4*)p = v0;
            *(float4*)(p + 4) = v1;
            float part = v0.x + v0.y + v0.z + v0.w + v1.x + v1.y + v1.z + v1.w;
            part += __shfl_down_sync(0xffffffffu, part, 2);
            part += __shfl_down_sync(0xffffffffu, part, 1);
            if ((lane & 3) == 0) atomicAdd(&Zsh[n], part);
        }
        __syncthreads();

        const float* Ast = As + (t & 1) * ASZ;
#pragma unroll
        for (int ks = 0; ks < BK; ks += 8) {
            unsigned a[2][4], bf[4][2];
#pragma unroll
            for (int mt = 0; mt < 2; mt++) {
                int m = wm + mt * 16 + g;
                a[mt][0] = __float_as_uint(Ast[m * SA + ks + tg]);
                a[mt][1] = __float_as_uint(Ast[(m + 8) * SA + ks + tg]);
                a[mt][2] = __float_as_uint(Ast[m * SA + ks + tg + 4]);
                a[mt][3] = __float_as_uint(Ast[(m + 8) * SA + ks + tg + 4]);
            }
#pragma unroll
            for (int nt = 0; nt < 4; nt++) {
                int n = wn + nt * 8 + g;
                bf[nt][0] = __float_as_uint(Bst[n * SB + ks + tg]);
                bf[nt][1] = __float_as_uint(Bst[n * SB + ks + tg + 4]);
            }
#pragma unroll
            for (int mt = 0; mt < 2; mt++)
#pragma unroll
                for (int nt = 0; nt < 4; nt++) {
                    asm volatile(
                        "mma.sync.aligned.m16n8k8.row.col.f32.tf32.tf32.f32 "
                        "{%0,%1,%2,%3}, {%4,%5,%6,%7}, {%8,%9}, {%0,%1,%2,%3};\n"
                        : "+f"(acc[mt][nt][0]), "+f"(acc[mt][nt][1]),
                          "+f"(acc[mt][nt][2]), "+f"(acc[mt][nt][3])
                        : "r"(a[mt][0]), "r"(a[mt][1]), "r"(a[mt][2]), "r"(a[mt][3]),
                          "r"(bf[nt][0]), "r"(bf[nt][1]));
                }
        }
        __syncthreads();
    }

#pragma unroll
    for (int mt = 0; mt < 2; mt++) {
        int row = wm + mt * 16 + g;
#pragma unroll
        for (int nt = 0; nt < 4; nt++) {
            int cl = wn + nt * 8 + tg * 2;
            float iz0 = 1.f / Zsh[cl], iz1 = 1.f / Zsh[cl + 1];
            int col = bn + cl;
            float2 v0 = make_float2(rnd_tf32(acc[mt][nt][0] * iz0),
                                    rnd_tf32(acc[mt][nt][1] * iz1));
            float2 v1 = make_float2(rnd_tf32(acc[mt][nt][2] * iz0),
                                    rnd_tf32(acc[mt][nt][3] * iz1));
            *(float2*)(Cp + (long)row * C + col)       = v0;
            *(float2*)(Cp + (long)(row + 8) * C + col) = v1;
        }
    }
}

__global__ __launch_bounds__(256)
void k_wo_all(PtrsWo p)
{
    int br, lt;
    br_from_x(blockIdx.x, br, lt);
    const int C = 64 << br;
    const int Coff = coff_of(br);
    gemm_core<128, false, false, false, false, true, false>(
        g_outpre + (long)8192 * Coff,
        p.Wo[br],
        p.out + (long)8192 * Coff,
        8192, C, C, blockIdx.y * 128, lt * 64, 0, 1.f, nullptr, nullptr);
}

// ---------------------------------------------------------------------------
// Launch sequence: 9 launches
// ---------------------------------------------------------------------------
extern "C" void kernel_launch(void* const* d_in, const int* in_sizes, int n_in,
                              void* d_out, int out_size)
{
    PtrsQt qp;
    PtrsWo wp;
    qp.Q[0] = (const float*)d_in[0];  qp.Q[1] = (const float*)d_in[1];
    qp.Q[2] = (const float*)d_in[2];  qp.Q[3] = (const float*)d_in[3];
    const float* KV = (const float*)d_in[4];
    const float* Wk = (const float*)d_in[5];
    const float* Wv = (const float*)d_in[6];
    qp.Wq[0] = (const float*)d_in[7];  qp.Wq[1] = (const float*)d_in[8];
    qp.Wq[2] = (const float*)d_in[9];  qp.Wq[3] = (const float*)d_in[10];
    wp.Wo[0] = (const float*)d_in[11]; wp.Wo[1] = (const float*)d_in[12];
    wp.Wo[2] = (const float*)d_in[13]; wp.Wo[3] = (const float*)d_in[14];
    wp.out = (float*)d_out;

    const int SM_NN   = (2 * (128 * 36 + 64 * 36)) * 4;          // 55296
    const int SM_TT   = (2 * (32 * 136 + 32 * 72)) * 4;          // 53248
    const int SM_TT64 = (2 * (32 * 72 + 32 * 72)) * 4;           // 36864
    const int SM_AV   = SM_NN + 128 * 4;                         // 55808

    cudaFuncSetAttribute(k_kv1,    cudaFuncAttributeMaxDynamicSharedMemorySize, SM_NN);
    cudaFuncSetAttribute(k_kv2,    cudaFuncAttributeMaxDynamicSharedMemorySize, SM_NN);
    cudaFuncSetAttribute(k_qt_all, cudaFuncAttributeMaxDynamicSharedMemorySize, SM_NN);
    cudaFuncSetAttribute(k_lg64,   cudaFuncAttributeMaxDynamicSharedMemorySize, SM_TT64);
    cudaFuncSetAttribute(k_lg_rest,cudaFuncAttributeMaxDynamicSharedMemorySize, SM_TT);
    cudaFuncSetAttribute(k_av_all, cudaFuncAttributeMaxDynamicSharedMemorySize, SM_AV);
    cudaFuncSetAttribute(k_wo_all, cudaFuncAttributeMaxDynamicSharedMemorySize, SM_NN);

    // 1) clear per-row maxima (sequence start; graph-replay safe)
    k_reset_rowmax<<<(GB * CSUM + 255) / 256, 256>>>(GB * CSUM);

    // 2-3) KV transform: Kt = KV @ Wk^T ; KVt = Kt @ Wv^T
    k_kv1<<<dim3(SDIM / 64, 1, GB), 256, SM_NN>>>(KV, Wk);
    k_kv2<<<dim3(SDIM / 64, 1, GB), 256, SM_NN>>>(Wv);

    // 4) all four Qt projections in one launch
    k_qt_all<<<dim3(15, 1, GB), 256, SM_NN>>>(qp);

    // 5-6) logits (+ fused stats/rowmax): C=64 (BM64) and C=128/256/512 merged
    k_lg64<<<dim3(SDIM / 64, 1, GB), 256, SM_TT64>>>();
    k_lg_rest<<<dim3(SDIM / 64, 7, GB), 256, SM_TT>>>();

    // 7) all per-slice rstd in one launch
    k_stats_all<<<1, 256>>>();

    // 8) all four softmax-AV GEMMs in one launch
    k_av_all<<<dim3(15, 1, GB), 256, SM_AV>>>();

    // 9) all four output projections in one launch
    k_wo_all<<<dim3(15, 64, 1), 256, SM_NN>>>(wp);
}